// round 1
// baseline (speedup 1.0000x reference)
#include <cuda_runtime.h>
#include <math.h>

// ---------------- problem constants ----------------
#define M_ROWS 4096      // B*S
#define HDIM   896
#define DHEAD  128
#define NHEADS 7
#define SEQ    2048
#define QKV_N  1152      // 7*128 + 128 + 128
#define IDIM   4864
#define BQ     64
#define BK     64
#define QSTRIDE 132      // padded smem stride (floats) for 128-wide tiles
#define PSTRIDE 65

// ---------------- scratch (device globals; no runtime alloc) ----------------
__device__ float g_h1  [M_ROWS * HDIM];
__device__ float g_qkv [M_ROWS * QKV_N];
__device__ float g_attn[M_ROWS * HDIM];
__device__ float g_x2  [M_ROWS * HDIM];
__device__ float g_h2  [M_ROWS * HDIM];
__device__ float g_up  [(size_t)M_ROWS * IDIM];
__device__ float g_wqkv[QKV_N * HDIM];
__device__ float g_bqkv[QKV_N];

// ---------------- RMSNorm: one block per row ----------------
__global__ void __launch_bounds__(256) rmsnorm_kernel(const float* __restrict__ x,
                                                      const float* __restrict__ w,
                                                      float* __restrict__ out)
{
    __shared__ float red[256];
    const int row = blockIdx.x;
    const float* xr = x + (size_t)row * HDIM;
    float ss = 0.f;
    for (int i = threadIdx.x; i < HDIM; i += 256) { float v = xr[i]; ss += v * v; }
    red[threadIdx.x] = ss;
    __syncthreads();
    for (int s = 128; s > 0; s >>= 1) {
        if (threadIdx.x < s) red[threadIdx.x] += red[threadIdx.x + s];
        __syncthreads();
    }
    const float inv = rsqrtf(red[0] / (float)HDIM + 1e-6f);
    float* orow = out + (size_t)row * HDIM;
    for (int i = threadIdx.x; i < HDIM; i += 256) orow[i] = xr[i] * inv * w[i];
}

// ---------------- NT GEMM: C[M,N] = A[M,K] @ B[N,K]^T  (+ epilogue) ----------
// MODE 0: + bias[n] (bias may be null)
// MODE 1: + aux[m,n]              (residual add)
// MODE 2: silu(acc) * aux[m,n]    (written to C, which may alias aux)
template<int MODE>
__global__ void __launch_bounds__(256) gemm_nt(const float* __restrict__ A,
                                               const float* __restrict__ B,
                                               const float* __restrict__ bias,
                                               const float* __restrict__ aux,
                                               float* __restrict__ C,
                                               int M, int N, int K)
{
    __shared__ float As[16][QSTRIDE];
    __shared__ float Bs[16][QSTRIDE];
    const int tid = threadIdx.x;
    const int tx = tid & 15, ty = tid >> 4;
    const int m0 = blockIdx.y * 128, n0 = blockIdx.x * 128;
    const float* Ap = A + (size_t)m0 * K;
    const float* Bp = B + (size_t)n0 * K;

    float acc[8][8];
#pragma unroll
    for (int i = 0; i < 8; i++)
#pragma unroll
        for (int j = 0; j < 8; j++) acc[i][j] = 0.f;

    for (int k0 = 0; k0 < K; k0 += 16) {
#pragma unroll
        for (int it = 0; it < 2; ++it) {
            const int f = tid + it * 256;   // 512 float4 per tile, coalesced
            const int r = f >> 2;
            const int c = (f & 3) << 2;
            float4 av = *(const float4*)(Ap + (size_t)r * K + k0 + c);
            As[c + 0][r] = av.x; As[c + 1][r] = av.y; As[c + 2][r] = av.z; As[c + 3][r] = av.w;
            float4 bv = *(const float4*)(Bp + (size_t)r * K + k0 + c);
            Bs[c + 0][r] = bv.x; Bs[c + 1][r] = bv.y; Bs[c + 2][r] = bv.z; Bs[c + 3][r] = bv.w;
        }
        __syncthreads();
#pragma unroll
        for (int kk = 0; kk < 16; ++kk) {
            float a[8], b[8];
            *(float4*)(a)     = *(const float4*)&As[kk][ty * 8];
            *(float4*)(a + 4) = *(const float4*)&As[kk][ty * 8 + 4];
            *(float4*)(b)     = *(const float4*)&Bs[kk][tx * 8];
            *(float4*)(b + 4) = *(const float4*)&Bs[kk][tx * 8 + 4];
#pragma unroll
            for (int i = 0; i < 8; i++)
#pragma unroll
                for (int j = 0; j < 8; j++) acc[i][j] = fmaf(a[i], b[j], acc[i][j]);
        }
        __syncthreads();
    }

#pragma unroll
    for (int i = 0; i < 8; i++) {
        const int m = m0 + ty * 8 + i;
        float* crow = C + (size_t)m * N;
        const float* arow = (MODE != 0) ? (aux + (size_t)m * N) : nullptr;
#pragma unroll
        for (int j = 0; j < 8; j++) {
            const int n = n0 + tx * 8 + j;
            float v = acc[i][j];
            if (MODE == 0) { if (bias) v += bias[n]; }
            else if (MODE == 1) { v += arow[n]; }
            else { v = v / (1.f + __expf(-v)) * arow[n]; }
            crow[n] = v;
        }
    }
}

// ---------------- RoPE on q (7 heads) and k (1 head) ----------------
__global__ void rope_kernel(float* __restrict__ qkv,
                            const float* __restrict__ cosT,
                            const float* __restrict__ sinT)
{
    const int row  = blockIdx.x;       // 0..4095
    const int unit = blockIdx.y;       // 0..6 = q heads, 7 = k
    const int d    = threadIdx.x;      // 0..63
    const int s    = row & (SEQ - 1);
    const float c  = cosT[s * DHEAD + d];
    const float sn = sinT[s * DHEAD + d];
    float* p = qkv + (size_t)row * QKV_N + (unit < NHEADS ? unit * DHEAD : HDIM);
    const float x1 = p[d], x2 = p[d + 64];
    p[d]      = x1 * c  - x2 * sn;
    p[d + 64] = x1 * sn + x2 * c;
}

// ---------------- causal flash attention (fp32, GQA: 1 kv head) -------------
__global__ void __launch_bounds__(256) flash_kernel(const float* __restrict__ qkv,
                                                    float* __restrict__ out)
{
    extern __shared__ float sm[];
    float* Qs = sm;                       // 64 x 132
    float* Ks = Qs + 64 * QSTRIDE;        // 64 x 132
    float* Vs = Ks + 64 * QSTRIDE;        // 64 x 132
    float* Ps = Vs + 64 * QSTRIDE;        // 64 x 65

    const int tid = threadIdx.x;
    const int tx = tid & 15, ty = tid >> 4;
    const int b = blockIdx.z, h = blockIdx.y;
    const int q0 = blockIdx.x * BQ;
    const float scale = 0.08838834764831845f;   // 1/sqrt(128)

    // load Q tile (pre-scaled)
    for (int f = tid; f < 64 * 32; f += 256) {
        const int r = f >> 5, c = (f & 31) << 2;
        float4 v = *(const float4*)(qkv + ((size_t)(b * SEQ + q0 + r)) * QKV_N + h * DHEAD + c);
        Qs[r * QSTRIDE + c]     = v.x * scale;
        Qs[r * QSTRIDE + c + 1] = v.y * scale;
        Qs[r * QSTRIDE + c + 2] = v.z * scale;
        Qs[r * QSTRIDE + c + 3] = v.w * scale;
    }

    float m_i[4], l_i[4], o[4][8];
#pragma unroll
    for (int i = 0; i < 4; i++) {
        m_i[i] = -1e30f; l_i[i] = 0.f;
#pragma unroll
        for (int j = 0; j < 8; j++) o[i][j] = 0.f;
    }

    const int jend = q0 / BK;
    for (int jt = 0; jt <= jend; ++jt) {
        __syncthreads();   // protect Ks/Vs/Ps reuse from previous iteration
        for (int f = tid; f < 64 * 32; f += 256) {
            const int r = f >> 5, c = (f & 31) << 2;
            const float* base = qkv + ((size_t)(b * SEQ + jt * BK + r)) * QKV_N;
            float4 kv = *(const float4*)(base + HDIM + c);
            Ks[r * QSTRIDE + c] = kv.x; Ks[r * QSTRIDE + c + 1] = kv.y;
            Ks[r * QSTRIDE + c + 2] = kv.z; Ks[r * QSTRIDE + c + 3] = kv.w;
            float4 vv = *(const float4*)(base + HDIM + DHEAD + c);
            Vs[r * QSTRIDE + c] = vv.x; Vs[r * QSTRIDE + c + 1] = vv.y;
            Vs[r * QSTRIDE + c + 2] = vv.z; Vs[r * QSTRIDE + c + 3] = vv.w;
        }
        __syncthreads();

        // S = Q @ K^T  — thread owns rows ty*4+i, cols tx+16*j (strided: 2-way max bank conflict)
        float s4[4][4];
#pragma unroll
        for (int i = 0; i < 4; i++)
#pragma unroll
            for (int j = 0; j < 4; j++) s4[i][j] = 0.f;

        for (int d = 0; d < 128; d += 4) {
            float4 qv[4], kv[4];
#pragma unroll
            for (int i = 0; i < 4; i++) qv[i] = *(const float4*)&Qs[(ty * 4 + i) * QSTRIDE + d];
#pragma unroll
            for (int j = 0; j < 4; j++) kv[j] = *(const float4*)&Ks[(tx + 16 * j) * QSTRIDE + d];
#pragma unroll
            for (int i = 0; i < 4; i++)
#pragma unroll
                for (int j = 0; j < 4; j++)
                    s4[i][j] += qv[i].x * kv[j].x + qv[i].y * kv[j].y
                              + qv[i].z * kv[j].z + qv[i].w * kv[j].w;
        }

        if (jt == jend) {  // diagonal tile: causal mask
#pragma unroll
            for (int i = 0; i < 4; i++)
#pragma unroll
                for (int j = 0; j < 4; j++)
                    if (jt * BK + tx + 16 * j > q0 + ty * 4 + i) s4[i][j] = -1e30f;
        }

        // online softmax (row groups = 16 consecutive lanes -> xor-shuffle reduce)
#pragma unroll
        for (int i = 0; i < 4; i++) {
            float rm = fmaxf(fmaxf(s4[i][0], s4[i][1]), fmaxf(s4[i][2], s4[i][3]));
#pragma unroll
            for (int off = 8; off >= 1; off >>= 1)
                rm = fmaxf(rm, __shfl_xor_sync(0xffffffffu, rm, off));
            const float mn = fmaxf(m_i[i], rm);
            const float alpha = __expf(m_i[i] - mn);
            m_i[i] = mn;
            float rs = 0.f;
#pragma unroll
            for (int j = 0; j < 4; j++) {
                const float p = __expf(s4[i][j] - mn);
                s4[i][j] = p; rs += p;
            }
#pragma unroll
            for (int off = 8; off >= 1; off >>= 1)
                rs += __shfl_xor_sync(0xffffffffu, rs, off);
            l_i[i] = l_i[i] * alpha + rs;
#pragma unroll
            for (int j = 0; j < 8; j++) o[i][j] *= alpha;
#pragma unroll
            for (int j = 0; j < 4; j++) Ps[(ty * 4 + i) * PSTRIDE + tx + 16 * j] = s4[i][j];
        }
        __syncthreads();

        // O += P @ V  — thread owns rows ty*4+i, cols tx*8..tx*8+7
#pragma unroll 4
        for (int kk = 0; kk < 64; ++kk) {
            float pp[4];
#pragma unroll
            for (int i = 0; i < 4; i++) pp[i] = Ps[(ty * 4 + i) * PSTRIDE + kk];
            const float4 v0 = *(const float4*)&Vs[kk * QSTRIDE + tx * 8];
            const float4 v1 = *(const float4*)&Vs[kk * QSTRIDE + tx * 8 + 4];
            const float vv[8] = {v0.x, v0.y, v0.z, v0.w, v1.x, v1.y, v1.z, v1.w};
#pragma unroll
            for (int i = 0; i < 4; i++)
#pragma unroll
                for (int j = 0; j < 8; j++) o[i][j] = fmaf(pp[i], vv[j], o[i][j]);
        }
    }

    // epilogue: normalize and write to packed (M, 896) layout
#pragma unroll
    for (int i = 0; i < 4; i++) {
        const float invl = 1.f / l_i[i];
        const size_t orow = ((size_t)(b * SEQ + q0 + ty * 4 + i)) * HDIM + h * DHEAD + tx * 8;
#pragma unroll
        for (int j = 0; j < 8; j++) out[orow + j] = o[i][j] * invl;
    }
}

// ---------------- launcher ----------------
extern "C" void kernel_launch(void* const* d_in, const int* in_sizes, int n_in,
                              void* d_out, int out_size)
{
    // Resolve input ordering: dict order vs reference-signature order.
    int iwq, ibq, iwk, ibk, iwv, ibv, iwo, iwg, iwu, iwd, iln1, iln2, icos, isin;
    if (n_in >= 2 && in_sizes[1] == SEQ * SEQ) {
        // signature order: hs, mask, cos, sin, wq, bq, wk, bk, wv, bv, wo, wg, wu, wd, ln1, ln2
        icos = 2; isin = 3; iwq = 4; ibq = 5; iwk = 6; ibk = 7; iwv = 8; ibv = 9;
        iwo = 10; iwg = 11; iwu = 12; iwd = 13; iln1 = 14; iln2 = 15;
    } else {
        // dict order: hs, wq, bq, wk, bk, wv, bv, wo, wg, wu, wd, ln1, ln2, mask, cos, sin
        iwq = 1; ibq = 2; iwk = 3; ibk = 4; iwv = 5; ibv = 6; iwo = 7; iwg = 8;
        iwu = 9; iwd = 10; iln1 = 11; iln2 = 12; icos = 14; isin = 15;
    }

    const float* hs   = (const float*)d_in[0];
    const float* wq   = (const float*)d_in[iwq];
    const float* bq   = (const float*)d_in[ibq];
    const float* wk   = (const float*)d_in[iwk];
    const float* bk   = (const float*)d_in[ibk];
    const float* wv   = (const float*)d_in[iwv];
    const float* bv   = (const float*)d_in[ibv];
    const float* wo   = (const float*)d_in[iwo];
    const float* wg   = (const float*)d_in[iwg];
    const float* wu   = (const float*)d_in[iwu];
    const float* wd   = (const float*)d_in[iwd];
    const float* ln1  = (const float*)d_in[iln1];
    const float* ln2  = (const float*)d_in[iln2];
    const float* cosT = (const float*)d_in[icos];
    const float* sinT = (const float*)d_in[isin];

    float *p_h1, *p_qkv, *p_attn, *p_x2, *p_h2, *p_up, *p_wqkv, *p_bqkv;
    cudaGetSymbolAddress((void**)&p_h1,   g_h1);
    cudaGetSymbolAddress((void**)&p_qkv,  g_qkv);
    cudaGetSymbolAddress((void**)&p_attn, g_attn);
    cudaGetSymbolAddress((void**)&p_x2,   g_x2);
    cudaGetSymbolAddress((void**)&p_h2,   g_h2);
    cudaGetSymbolAddress((void**)&p_up,   g_up);
    cudaGetSymbolAddress((void**)&p_wqkv, g_wqkv);
    cudaGetSymbolAddress((void**)&p_bqkv, g_bqkv);

    // concat wq|wk|wv and bq|bk|bv (row-major (out,in) => contiguous concat)
    cudaMemcpyAsync(p_wqkv,                               wq, (size_t)HDIM  * HDIM * 4, cudaMemcpyDeviceToDevice, 0);
    cudaMemcpyAsync(p_wqkv + (size_t)HDIM * HDIM,         wk, (size_t)DHEAD * HDIM * 4, cudaMemcpyDeviceToDevice, 0);
    cudaMemcpyAsync(p_wqkv + (size_t)(HDIM+DHEAD) * HDIM, wv, (size_t)DHEAD * HDIM * 4, cudaMemcpyDeviceToDevice, 0);
    cudaMemcpyAsync(p_bqkv,               bq, HDIM  * 4, cudaMemcpyDeviceToDevice, 0);
    cudaMemcpyAsync(p_bqkv + HDIM,        bk, DHEAD * 4, cudaMemcpyDeviceToDevice, 0);
    cudaMemcpyAsync(p_bqkv + HDIM + DHEAD,bv, DHEAD * 4, cudaMemcpyDeviceToDevice, 0);

    // 1) rmsnorm1
    rmsnorm_kernel<<<M_ROWS, 256>>>(hs, ln1, p_h1);
    // 2) fused QKV projection (N = 1152)
    gemm_nt<0><<<dim3(QKV_N / 128, M_ROWS / 128), 256>>>(p_h1, p_wqkv, p_bqkv, nullptr, p_qkv,
                                                         M_ROWS, QKV_N, HDIM);
    // 3) RoPE on q heads + k
    rope_kernel<<<dim3(M_ROWS, NHEADS + 1), 64>>>(p_qkv, cosT, sinT);
    // 4) causal flash attention
    const int flash_smem = (3 * 64 * QSTRIDE + 64 * PSTRIDE) * 4;
    cudaFuncSetAttribute(flash_kernel, cudaFuncAttributeMaxDynamicSharedMemorySize, flash_smem);
    flash_kernel<<<dim3(SEQ / BQ, NHEADS, 2), 256, flash_smem>>>(p_qkv, p_attn);
    // 5) O projection + residual
    gemm_nt<1><<<dim3(HDIM / 128, M_ROWS / 128), 256>>>(p_attn, wo, nullptr, hs, p_x2,
                                                        M_ROWS, HDIM, HDIM);
    // 6) rmsnorm2
    rmsnorm_kernel<<<M_ROWS, 256>>>(p_x2, ln2, p_h2);
    // 7) up projection
    gemm_nt<0><<<dim3(IDIM / 128, M_ROWS / 128), 256>>>(p_h2, wu, nullptr, nullptr, p_up,
                                                        M_ROWS, IDIM, HDIM);
    // 8) gate projection with fused silu(gate)*up, in place into g_up
    gemm_nt<2><<<dim3(IDIM / 128, M_ROWS / 128), 256>>>(p_h2, wg, nullptr, p_up, p_up,
                                                        M_ROWS, IDIM, HDIM);
    // 9) down projection + residual -> output
    gemm_nt<1><<<dim3(HDIM / 128, M_ROWS / 128), 256>>>(p_up, wd, nullptr, p_x2, (float*)d_out,
                                                        M_ROWS, HDIM, IDIM);
    (void)out_size;
}

// round 4
// speedup vs baseline: 1.4998x; 1.4998x over previous
#include <cuda_runtime.h>
#include <math.h>
#include <stdint.h>

// ---------------- problem constants ----------------
#define M_ROWS 4096      // B*S
#define HDIM   896
#define DHEAD  128
#define NHEADS 7
#define SEQ    2048
#define QKV_N  1152      // 7*128 + 128 + 128
#define IDIM   4864
#define BQ     64
#define BK     64
#define QSTRIDE 132
#define PSTRIDE 65

#define GSTRIDE 36       // smem stride (floats) for mma tiles: bank = lane (conflict-free)

// ---------------- scratch (device globals; no runtime alloc) ----------------
__device__ float g_h1  [M_ROWS * HDIM];
__device__ float g_qkv [M_ROWS * QKV_N];
__device__ float g_attn[M_ROWS * HDIM];
__device__ float g_x2  [M_ROWS * HDIM];
__device__ float g_h2  [M_ROWS * HDIM];
__device__ float g_up  [(size_t)M_ROWS * IDIM];
__device__ float g_wqkv[QKV_N * HDIM];
__device__ float g_bqkv[QKV_N];

// ---------------- RMSNorm ----------------
__global__ void __launch_bounds__(256) rmsnorm_kernel(const float* __restrict__ x,
                                                      const float* __restrict__ w,
                                                      float* __restrict__ out)
{
    __shared__ float red[256];
    const int row = blockIdx.x;
    const float* xr = x + (size_t)row * HDIM;
    float ss = 0.f;
    for (int i = threadIdx.x; i < HDIM; i += 256) { float v = xr[i]; ss += v * v; }
    red[threadIdx.x] = ss;
    __syncthreads();
    for (int s = 128; s > 0; s >>= 1) {
        if (threadIdx.x < s) red[threadIdx.x] += red[threadIdx.x + s];
        __syncthreads();
    }
    const float inv = rsqrtf(red[0] / (float)HDIM + 1e-6f);
    float* orow = out + (size_t)row * HDIM;
    for (int i = threadIdx.x; i < HDIM; i += 256) orow[i] = xr[i] * inv * w[i];
}

// ---------------- tf32 helpers ----------------
__device__ __forceinline__ uint32_t to_tf32(float f) {
    uint32_t r;
    asm("cvt.rna.tf32.f32 %0, %1;" : "=r"(r) : "f"(f));
    return r;
}
__device__ __forceinline__ void mma_16x8x8(float* c, const uint32_t* a, const uint32_t* b) {
    asm volatile(
        "mma.sync.aligned.m16n8k8.row.col.f32.tf32.tf32.f32 "
        "{%0,%1,%2,%3}, {%4,%5,%6,%7}, {%8,%9}, {%0,%1,%2,%3};"
        : "+f"(c[0]), "+f"(c[1]), "+f"(c[2]), "+f"(c[3])
        : "r"(a[0]), "r"(a[1]), "r"(a[2]), "r"(a[3]), "r"(b[0]), "r"(b[1]));
}

// ---------------- tf32 mma.sync NT GEMM: C[M,N] = A[M,K] @ B[N,K]^T + epi ---
// 128x128 CTA tile, 256 thr (2x4 warps of 64x32), BK=32, double-buffered smem.
// MODE 0: +bias[n] (nullable). MODE 1: +aux[m,n]. MODE 2: silu(acc)*aux[m,n].
template<int MODE>
__global__ void __launch_bounds__(256) gemm_mma(const float* __restrict__ A,
                                                const float* __restrict__ B,
                                                const float* __restrict__ bias,
                                                const float* __restrict__ aux,
                                                float* __restrict__ C,
                                                int M, int N, int K)
{
    extern __shared__ float sm[];
    float* As[2] = { sm,                   sm + 128 * GSTRIDE };
    float* Bs[2] = { sm + 2 * 128 * GSTRIDE, sm + 3 * 128 * GSTRIDE };

    const int tid = threadIdx.x;
    const int wid = tid >> 5, lane = tid & 31;
    const int lq = lane >> 2, lr = lane & 3;
    const int warp_m = wid >> 2, warp_n = wid & 3;           // 2 x 4
    const int rowbase = warp_m * 64, colbase = warp_n * 32;
    const int m0 = blockIdx.y * 128, n0 = blockIdx.x * 128;

    // producer indexing: 4 float4 per thread per operand per chunk
    const int pr = tid >> 3;            // rows tid/8 .. step 32
    const int pc = (tid & 7) << 2;      // float col within 32-wide chunk

    float acc[4][4][4];
#pragma unroll
    for (int i = 0; i < 4; i++)
#pragma unroll
        for (int j = 0; j < 4; j++)
#pragma unroll
            for (int q = 0; q < 4; q++) acc[i][j][q] = 0.f;

    const int nch = K >> 5;
    float4 rA[4], rB[4];

    // preload chunk 0
    {
        const float* Ap = A + (size_t)m0 * K;
        const float* Bp = B + (size_t)n0 * K;
#pragma unroll
        for (int p = 0; p < 4; ++p) {
            rA[p] = *(const float4*)(Ap + (size_t)(pr + p * 32) * K + pc);
            rB[p] = *(const float4*)(Bp + (size_t)(pr + p * 32) * K + pc);
        }
#pragma unroll
        for (int p = 0; p < 4; ++p) {
            float* a = &As[0][(pr + p * 32) * GSTRIDE + pc];
            a[0] = __uint_as_float(to_tf32(rA[p].x)); a[1] = __uint_as_float(to_tf32(rA[p].y));
            a[2] = __uint_as_float(to_tf32(rA[p].z)); a[3] = __uint_as_float(to_tf32(rA[p].w));
            float* b = &Bs[0][(pr + p * 32) * GSTRIDE + pc];
            b[0] = __uint_as_float(to_tf32(rB[p].x)); b[1] = __uint_as_float(to_tf32(rB[p].y));
            b[2] = __uint_as_float(to_tf32(rB[p].z)); b[3] = __uint_as_float(to_tf32(rB[p].w));
        }
    }
    __syncthreads();

    for (int ch = 0; ch < nch; ++ch) {
        const int buf = ch & 1;
        // prefetch next chunk into registers (overlaps with compute below)
        if (ch + 1 < nch) {
            const float* Ap = A + (size_t)m0 * K + (ch + 1) * 32;
            const float* Bp = B + (size_t)n0 * K + (ch + 1) * 32;
#pragma unroll
            for (int p = 0; p < 4; ++p) {
                rA[p] = *(const float4*)(Ap + (size_t)(pr + p * 32) * K + pc);
                rB[p] = *(const float4*)(Bp + (size_t)(pr + p * 32) * K + pc);
            }
        }

        // compute: 4 k-steps of m16n8k8
        const float* Aw = As[buf];
        const float* Bw = Bs[buf];
#pragma unroll
        for (int ks = 0; ks < 4; ++ks) {
            uint32_t af[4][4], bf[4][2];
#pragma unroll
            for (int i = 0; i < 4; ++i) {
                const int base = (rowbase + i * 16 + lq) * GSTRIDE + ks * 8 + lr;
                af[i][0] = __float_as_uint(Aw[base]);
                af[i][1] = __float_as_uint(Aw[base + 8 * GSTRIDE]);
                af[i][2] = __float_as_uint(Aw[base + 4]);
                af[i][3] = __float_as_uint(Aw[base + 8 * GSTRIDE + 4]);
            }
#pragma unroll
            for (int j = 0; j < 4; ++j) {
                const int base = (colbase + j * 8 + lq) * GSTRIDE + ks * 8 + lr;
                bf[j][0] = __float_as_uint(Bw[base]);
                bf[j][1] = __float_as_uint(Bw[base + 4]);
            }
#pragma unroll
            for (int i = 0; i < 4; ++i)
#pragma unroll
                for (int j = 0; j < 4; ++j)
                    mma_16x8x8(acc[i][j], af[i], bf[j]);
        }
        __syncthreads();

        if (ch + 1 < nch) {
            const int nb = buf ^ 1;
#pragma unroll
            for (int p = 0; p < 4; ++p) {
                float* a = &As[nb][(pr + p * 32) * GSTRIDE + pc];
                a[0] = __uint_as_float(to_tf32(rA[p].x)); a[1] = __uint_as_float(to_tf32(rA[p].y));
                a[2] = __uint_as_float(to_tf32(rA[p].z)); a[3] = __uint_as_float(to_tf32(rA[p].w));
                float* b = &Bs[nb][(pr + p * 32) * GSTRIDE + pc];
                b[0] = __uint_as_float(to_tf32(rB[p].x)); b[1] = __uint_as_float(to_tf32(rB[p].y));
                b[2] = __uint_as_float(to_tf32(rB[p].z)); b[3] = __uint_as_float(to_tf32(rB[p].w));
            }
            __syncthreads();
        }
    }

    // epilogue: c fragment (i,j): rows m0+rowbase+i*16+lq (+8), cols n0+colbase+j*8+2*lr (+1)
#pragma unroll
    for (int i = 0; i < 4; ++i) {
#pragma unroll
        for (int half = 0; half < 2; ++half) {
            const int m = m0 + rowbase + i * 16 + lq + half * 8;
            float* crow = C + (size_t)m * N;
            const float* arow = (MODE != 0) ? (aux + (size_t)m * N) : nullptr;
#pragma unroll
            for (int j = 0; j < 4; ++j) {
                const int n = n0 + colbase + j * 8 + 2 * lr;
                float v0 = acc[i][j][half * 2 + 0];
                float v1 = acc[i][j][half * 2 + 1];
                if (MODE == 0) {
                    if (bias) { v0 += bias[n]; v1 += bias[n + 1]; }
                } else if (MODE == 1) {
                    v0 += arow[n]; v1 += arow[n + 1];
                } else {
                    v0 = v0 / (1.f + __expf(-v0)) * arow[n];
                    v1 = v1 / (1.f + __expf(-v1)) * arow[n + 1];
                }
                float2 o2; o2.x = v0; o2.y = v1;
                *(float2*)(crow + n) = o2;
            }
        }
    }
}

// ---------------- RoPE on q (7 heads) and k (1 head) ----------------
__global__ void rope_kernel(float* __restrict__ qkv,
                            const float* __restrict__ cosT,
                            const float* __restrict__ sinT)
{
    const int row  = blockIdx.x;
    const int unit = blockIdx.y;
    const int d    = threadIdx.x;
    const int s    = row & (SEQ - 1);
    const float c  = cosT[s * DHEAD + d];
    const float sn = sinT[s * DHEAD + d];
    float* p = qkv + (size_t)row * QKV_N + (unit < NHEADS ? unit * DHEAD : HDIM);
    const float x1 = p[d], x2 = p[d + 64];
    p[d]      = x1 * c  - x2 * sn;
    p[d + 64] = x1 * sn + x2 * c;
}

// ---------------- causal flash attention (fp32, GQA: 1 kv head) -------------
__global__ void __launch_bounds__(256) flash_kernel(const float* __restrict__ qkv,
                                                    float* __restrict__ out)
{
    extern __shared__ float sm[];
    float* Qs = sm;
    float* Ks = Qs + 64 * QSTRIDE;
    float* Vs = Ks + 64 * QSTRIDE;
    float* Ps = Vs + 64 * QSTRIDE;

    const int tid = threadIdx.x;
    const int tx = tid & 15, ty = tid >> 4;
    const int b = blockIdx.z, h = blockIdx.y;
    const int q0 = blockIdx.x * BQ;
    const float scale = 0.08838834764831845f;

    for (int f = tid; f < 64 * 32; f += 256) {
        const int r = f >> 5, c = (f & 31) << 2;
        float4 v = *(const float4*)(qkv + ((size_t)(b * SEQ + q0 + r)) * QKV_N + h * DHEAD + c);
        Qs[r * QSTRIDE + c]     = v.x * scale;
        Qs[r * QSTRIDE + c + 1] = v.y * scale;
        Qs[r * QSTRIDE + c + 2] = v.z * scale;
        Qs[r * QSTRIDE + c + 3] = v.w * scale;
    }

    float m_i[4], l_i[4], o[4][8];
#pragma unroll
    for (int i = 0; i < 4; i++) {
        m_i[i] = -1e30f; l_i[i] = 0.f;
#pragma unroll
        for (int j = 0; j < 8; j++) o[i][j] = 0.f;
    }

    const int jend = q0 / BK;
    for (int jt = 0; jt <= jend; ++jt) {
        __syncthreads();
        for (int f = tid; f < 64 * 32; f += 256) {
            const int r = f >> 5, c = (f & 31) << 2;
            const float* base = qkv + ((size_t)(b * SEQ + jt * BK + r)) * QKV_N;
            float4 kv = *(const float4*)(base + HDIM + c);
            Ks[r * QSTRIDE + c] = kv.x; Ks[r * QSTRIDE + c + 1] = kv.y;
            Ks[r * QSTRIDE + c + 2] = kv.z; Ks[r * QSTRIDE + c + 3] = kv.w;
            float4 vv = *(const float4*)(base + HDIM + DHEAD + c);
            Vs[r * QSTRIDE + c] = vv.x; Vs[r * QSTRIDE + c + 1] = vv.y;
            Vs[r * QSTRIDE + c + 2] = vv.z; Vs[r * QSTRIDE + c + 3] = vv.w;
        }
        __syncthreads();

        float s4[4][4];
#pragma unroll
        for (int i = 0; i < 4; i++)
#pragma unroll
            for (int j = 0; j < 4; j++) s4[i][j] = 0.f;

        for (int d = 0; d < 128; d += 4) {
            float4 qv[4], kv[4];
#pragma unroll
            for (int i = 0; i < 4; i++) qv[i] = *(const float4*)&Qs[(ty * 4 + i) * QSTRIDE + d];
#pragma unroll
            for (int j = 0; j < 4; j++) kv[j] = *(const float4*)&Ks[(tx + 16 * j) * QSTRIDE + d];
#pragma unroll
            for (int i = 0; i < 4; i++)
#pragma unroll
                for (int j = 0; j < 4; j++)
                    s4[i][j] += qv[i].x * kv[j].x + qv[i].y * kv[j].y
                              + qv[i].z * kv[j].z + qv[i].w * kv[j].w;
        }

        if (jt == jend) {
#pragma unroll
            for (int i = 0; i < 4; i++)
#pragma unroll
                for (int j = 0; j < 4; j++)
                    if (jt * BK + tx + 16 * j > q0 + ty * 4 + i) s4[i][j] = -1e30f;
        }

#pragma unroll
        for (int i = 0; i < 4; i++) {
            float rm = fmaxf(fmaxf(s4[i][0], s4[i][1]), fmaxf(s4[i][2], s4[i][3]));
#pragma unroll
            for (int off = 8; off >= 1; off >>= 1)
                rm = fmaxf(rm, __shfl_xor_sync(0xffffffffu, rm, off));
            const float mn = fmaxf(m_i[i], rm);
            const float alpha = __expf(m_i[i] - mn);
            m_i[i] = mn;
            float rs = 0.f;
#pragma unroll
            for (int j = 0; j < 4; j++) {
                const float p = __expf(s4[i][j] - mn);
                s4[i][j] = p; rs += p;
            }
#pragma unroll
            for (int off = 8; off >= 1; off >>= 1)
                rs += __shfl_xor_sync(0xffffffffu, rs, off);
            l_i[i] = l_i[i] * alpha + rs;
#pragma unroll
            for (int j = 0; j < 8; j++) o[i][j] *= alpha;
#pragma unroll
            for (int j = 0; j < 4; j++) Ps[(ty * 4 + i) * PSTRIDE + tx + 16 * j] = s4[i][j];
        }
        __syncthreads();

#pragma unroll 4
        for (int kk = 0; kk < 64; ++kk) {
            float pp[4];
#pragma unroll
            for (int i = 0; i < 4; i++) pp[i] = Ps[(ty * 4 + i) * PSTRIDE + kk];
            const float4 v0 = *(const float4*)&Vs[kk * QSTRIDE + tx * 8];
            const float4 v1 = *(const float4*)&Vs[kk * QSTRIDE + tx * 8 + 4];
            const float vv[8] = {v0.x, v0.y, v0.z, v0.w, v1.x, v1.y, v1.z, v1.w};
#pragma unroll
            for (int i = 0; i < 4; i++)
#pragma unroll
                for (int j = 0; j < 8; j++) o[i][j] = fmaf(pp[i], vv[j], o[i][j]);
        }
    }

#pragma unroll
    for (int i = 0; i < 4; i++) {
        const float invl = 1.f / l_i[i];
        const size_t orow = ((size_t)(b * SEQ + q0 + ty * 4 + i)) * HDIM + h * DHEAD + tx * 8;
#pragma unroll
        for (int j = 0; j < 8; j++) out[orow + j] = o[i][j] * invl;
    }
}

// ---------------- launcher ----------------
extern "C" void kernel_launch(void* const* d_in, const int* in_sizes, int n_in,
                              void* d_out, int out_size)
{
    int iwq, ibq, iwk, ibk, iwv, ibv, iwo, iwg, iwu, iwd, iln1, iln2, icos, isin;
    if (n_in >= 2 && in_sizes[1] == SEQ * SEQ) {
        icos = 2; isin = 3; iwq = 4; ibq = 5; iwk = 6; ibk = 7; iwv = 8; ibv = 9;
        iwo = 10; iwg = 11; iwu = 12; iwd = 13; iln1 = 14; iln2 = 15;
    } else {
        iwq = 1; ibq = 2; iwk = 3; ibk = 4; iwv = 5; ibv = 6; iwo = 7; iwg = 8;
        iwu = 9; iwd = 10; iln1 = 11; iln2 = 12; icos = 14; isin = 15;
    }

    const float* hs   = (const float*)d_in[0];
    const float* wq   = (const float*)d_in[iwq];
    const float* bq   = (const float*)d_in[ibq];
    const float* wk   = (const float*)d_in[iwk];
    const float* bk   = (const float*)d_in[ibk];
    const float* wv   = (const float*)d_in[iwv];
    const float* bv   = (const float*)d_in[ibv];
    const float* wo   = (const float*)d_in[iwo];
    const float* wg   = (const float*)d_in[iwg];
    const float* wu   = (const float*)d_in[iwu];
    const float* wd   = (const float*)d_in[iwd];
    const float* ln1  = (const float*)d_in[iln1];
    const float* ln2  = (const float*)d_in[iln2];
    const float* cosT = (const float*)d_in[icos];
    const float* sinT = (const float*)d_in[isin];

    float *p_h1, *p_qkv, *p_attn, *p_x2, *p_h2, *p_up, *p_wqkv, *p_bqkv;
    cudaGetSymbolAddress((void**)&p_h1,   g_h1);
    cudaGetSymbolAddress((void**)&p_qkv,  g_qkv);
    cudaGetSymbolAddress((void**)&p_attn, g_attn);
    cudaGetSymbolAddress((void**)&p_x2,   g_x2);
    cudaGetSymbolAddress((void**)&p_h2,   g_h2);
    cudaGetSymbolAddress((void**)&p_up,   g_up);
    cudaGetSymbolAddress((void**)&p_wqkv, g_wqkv);
    cudaGetSymbolAddress((void**)&p_bqkv, g_bqkv);

    cudaMemcpyAsync(p_wqkv,                                 wq, (size_t)HDIM  * HDIM * 4, cudaMemcpyDeviceToDevice, 0);
    cudaMemcpyAsync(p_wqkv + (size_t)HDIM * HDIM,           wk, (size_t)DHEAD * HDIM * 4, cudaMemcpyDeviceToDevice, 0);
    cudaMemcpyAsync(p_wqkv + (size_t)(HDIM + DHEAD) * HDIM, wv, (size_t)DHEAD * HDIM * 4, cudaMemcpyDeviceToDevice, 0);
    cudaMemcpyAsync(p_bqkv,                bq, HDIM  * 4, cudaMemcpyDeviceToDevice, 0);
    cudaMemcpyAsync(p_bqkv + HDIM,         bk, DHEAD * 4, cudaMemcpyDeviceToDevice, 0);
    cudaMemcpyAsync(p_bqkv + HDIM + DHEAD, bv, DHEAD * 4, cudaMemcpyDeviceToDevice, 0);

    const int smem_gemm = 4 * 128 * GSTRIDE * 4;   // 73728 B (double-buffered A+B)
    cudaFuncSetAttribute(gemm_mma<0>, cudaFuncAttributeMaxDynamicSharedMemorySize, smem_gemm);
    cudaFuncSetAttribute(gemm_mma<1>, cudaFuncAttributeMaxDynamicSharedMemorySize, smem_gemm);
    cudaFuncSetAttribute(gemm_mma<2>, cudaFuncAttributeMaxDynamicSharedMemorySize, smem_gemm);

    // 1) rmsnorm1
    rmsnorm_kernel<<<M_ROWS, 256>>>(hs, ln1, p_h1);
    // 2) fused QKV projection
    gemm_mma<0><<<dim3(QKV_N / 128, M_ROWS / 128), 256, smem_gemm>>>(
        p_h1, p_wqkv, p_bqkv, nullptr, p_qkv, M_ROWS, QKV_N, HDIM);
    // 3) RoPE
    rope_kernel<<<dim3(M_ROWS, NHEADS + 1), 64>>>(p_qkv, cosT, sinT);
    // 4) flash attention
    const int flash_smem = (3 * 64 * QSTRIDE + 64 * PSTRIDE) * 4;
    cudaFuncSetAttribute(flash_kernel, cudaFuncAttributeMaxDynamicSharedMemorySize, flash_smem);
    flash_kernel<<<dim3(SEQ / BQ, NHEADS, 2), 256, flash_smem>>>(p_qkv, p_attn);
    // 5) O projection + residual
    gemm_mma<1><<<dim3(HDIM / 128, M_ROWS / 128), 256, smem_gemm>>>(
        p_attn, wo, nullptr, hs, p_x2, M_ROWS, HDIM, HDIM);
    // 6) rmsnorm2
    rmsnorm_kernel<<<M_ROWS, 256>>>(p_x2, ln2, p_h2);
    // 7) up projection
    gemm_mma<0><<<dim3(IDIM / 128, M_ROWS / 128), 256, smem_gemm>>>(
        p_h2, wu, nullptr, nullptr, p_up, M_ROWS, IDIM, HDIM);
    // 8) gate projection + fused silu(gate)*up, in place
    gemm_mma<2><<<dim3(IDIM / 128, M_ROWS / 128), 256, smem_gemm>>>(
        p_h2, wg, nullptr, p_up, p_up, M_ROWS, IDIM, HDIM);
    // 9) down projection + residual -> output
    gemm_mma<1><<<dim3(HDIM / 128, M_ROWS / 128), 256, smem_gemm>>>(
        p_up, wd, nullptr, p_x2, (float*)d_out, M_ROWS, HDIM, IDIM);
    (void)out_size;
}

// round 11
// speedup vs baseline: 1.9622x; 1.3084x over previous
#include <cuda_runtime.h>
#include <math.h>
#include <stdint.h>

// ---------------- problem constants ----------------
#define M_ROWS 4096      // B*S
#define HDIM   896
#define DHEAD  128
#define NHEADS 7
#define SEQ    2048
#define QKV_N  1152      // 7*128 + 128 + 128
#define IDIM   4864
#define BQ     64
#define BK     64
#define QSTRIDE 132      // flash smem stride
#define PSTRIDE 65

#define GSTRIDE 36       // gemm smem stride (floats): bank = lane for fragment loads

// ---------------- scratch (device globals; no runtime alloc) ----------------
__device__ float g_h1  [M_ROWS * HDIM];
__device__ float g_qkv [M_ROWS * QKV_N];
__device__ float g_attn[M_ROWS * HDIM];
__device__ float g_x2  [M_ROWS * HDIM];
__device__ float g_h2  [M_ROWS * HDIM];
__device__ float g_up  [(size_t)M_ROWS * IDIM];
__device__ float g_wqkv[QKV_N * HDIM];
__device__ float g_bqkv[QKV_N];
// rounded weight copies: wo | wg | wu | wd
#define WO_OFF 0
#define WG_OFF (HDIM * HDIM)
#define WU_OFF (WG_OFF + IDIM * HDIM)
#define WD_OFF (WU_OFF + IDIM * HDIM)
#define WRND_TOTAL (WD_OFF + IDIM * HDIM)
__device__ float g_wrnd[WRND_TOTAL];

// ---------------- helpers ----------------
__device__ __forceinline__ uint32_t to_tf32(float f) {
    uint32_t r;
    asm("cvt.rna.tf32.f32 %0, %1;" : "=r"(r) : "f"(f));
    return r;
}
__device__ __forceinline__ float rndf(float f) { return __uint_as_float(to_tf32(f)); }
__device__ __forceinline__ void mma_16x8x8(float* c, const uint32_t* a, const uint32_t* b) {
    asm volatile(
        "mma.sync.aligned.m16n8k8.row.col.f32.tf32.tf32.f32 "
        "{%0,%1,%2,%3}, {%4,%5,%6,%7}, {%8,%9}, {%0,%1,%2,%3};"
        : "+f"(c[0]), "+f"(c[1]), "+f"(c[2]), "+f"(c[3])
        : "r"(a[0]), "r"(a[1]), "r"(a[2]), "r"(a[3]), "r"(b[0]), "r"(b[1]));
}
__device__ __forceinline__ uint32_t smem_u32(const void* p) {
    uint32_t a;
    asm("{ .reg .u64 t; cvta.to.shared.u64 t, %1; cvt.u32.u64 %0, t; }" : "=r"(a) : "l"(p));
    return a;
}
__device__ __forceinline__ void cp16(uint32_t dst, const float* src) {
    asm volatile("cp.async.cg.shared.global [%0], [%1], 16;" :: "r"(dst), "l"(src));
}

// ---------------- tf32 rounding kernel (weights) ----------------
__global__ void __launch_bounds__(256) round_tf32_kernel(const float* __restrict__ in,
                                                         float* __restrict__ out, int n4)
{
    const int i = blockIdx.x * 256 + threadIdx.x;
    if (i < n4) {
        float4 v = ((const float4*)in)[i];
        float4 o;
        o.x = rndf(v.x); o.y = rndf(v.y); o.z = rndf(v.z); o.w = rndf(v.w);
        ((float4*)out)[i] = o;
    }
}

// ---------------- RMSNorm (output rounded to tf32: pure GEMM input) --------
__global__ void __launch_bounds__(256) rmsnorm_kernel(const float* __restrict__ x,
                                                      const float* __restrict__ w,
                                                      float* __restrict__ out)
{
    __shared__ float red[256];
    const int row = blockIdx.x;
    const float* xr = x + (size_t)row * HDIM;
    float ss = 0.f;
    for (int i = threadIdx.x; i < HDIM; i += 256) { float v = xr[i]; ss += v * v; }
    red[threadIdx.x] = ss;
    __syncthreads();
    for (int s = 128; s > 0; s >>= 1) {
        if (threadIdx.x < s) red[threadIdx.x] += red[threadIdx.x + s];
        __syncthreads();
    }
    const float inv = rsqrtf(red[0] / (float)HDIM + 1e-6f);
    float* orow = out + (size_t)row * HDIM;
    for (int i = threadIdx.x; i < HDIM; i += 256) orow[i] = rndf(xr[i] * inv * w[i]);
}

// ---------------- tf32 mma GEMM, cp.async 3-stage: C = A @ B^T + epi -------
// Inputs A,B must already be tf32-rounded. 128x128 tile, 256 thr, BK=32.
// MODE 0: +bias[n] (nullable). MODE 1: +aux[m,n]. MODE 2: silu(acc)*aux -> rounded.
template<int MODE>
__global__ void __launch_bounds__(256) gemm_ca(const float* __restrict__ A,
                                               const float* __restrict__ B,
                                               const float* __restrict__ bias,
                                               const float* __restrict__ aux,
                                               float* __restrict__ C,
                                               int M, int N, int K)
{
    extern __shared__ float sm[];
    const uint32_t sbase = smem_u32(sm);
    constexpr uint32_t STG = 2 * 128 * GSTRIDE;   // floats per stage (A+B)

    const int tid = threadIdx.x;
    const int wid = tid >> 5, lane = tid & 31;
    const int lq = lane >> 2, lr = lane & 3;
    const int warp_m = wid >> 2, warp_n = wid & 3;
    const int rowbase = warp_m * 64, colbase = warp_n * 32;
    const int m0 = blockIdx.y * 128, n0 = blockIdx.x * 128;

    const int pr = tid >> 3;          // 0..31
    const int pc = (tid & 7) << 2;    // 0..28

    float acc[4][4][4];
#pragma unroll
    for (int i = 0; i < 4; i++)
#pragma unroll
        for (int j = 0; j < 4; j++)
#pragma unroll
            for (int q = 0; q < 4; q++) acc[i][j][q] = 0.f;

    const int nch = K >> 5;
    const float* Abase = A + (size_t)m0 * K;
    const float* Bbase = B + (size_t)n0 * K;

#define ISSUE(CH, S) do { \
        const float* Ap_ = Abase + (CH) * 32; \
        const float* Bp_ = Bbase + (CH) * 32; \
        const uint32_t sA_ = sbase + (S) * STG * 4; \
        const uint32_t sB_ = sA_ + 128 * GSTRIDE * 4; \
        _Pragma("unroll") \
        for (int p_ = 0; p_ < 4; ++p_) { \
            const int r_ = pr + p_ * 32; \
            cp16(sA_ + (uint32_t)(r_ * GSTRIDE + pc) * 4, Ap_ + (size_t)r_ * K + pc); \
            cp16(sB_ + (uint32_t)(r_ * GSTRIDE + pc) * 4, Bp_ + (size_t)r_ * K + pc); \
        } \
    } while (0)

    // prologue: stages 0,1
    ISSUE(0, 0);
    asm volatile("cp.async.commit_group;");
    if (nch > 1) ISSUE(1, 1);
    asm volatile("cp.async.commit_group;");

    for (int ch = 0; ch < nch; ++ch) {
        if (ch + 2 < nch) ISSUE(ch + 2, (ch + 2) % 3);
        asm volatile("cp.async.commit_group;");
        asm volatile("cp.async.wait_group 2;");
        __syncthreads();

        const float* Aw = sm + (ch % 3) * STG;
        const float* Bw = Aw + 128 * GSTRIDE;
#pragma unroll
        for (int ks = 0; ks < 4; ++ks) {
            uint32_t af[4][4], bf[4][2];
#pragma unroll
            for (int i = 0; i < 4; ++i) {
                const int base = (rowbase + i * 16 + lq) * GSTRIDE + ks * 8 + lr;
                af[i][0] = __float_as_uint(Aw[base]);
                af[i][1] = __float_as_uint(Aw[base + 8 * GSTRIDE]);
                af[i][2] = __float_as_uint(Aw[base + 4]);
                af[i][3] = __float_as_uint(Aw[base + 8 * GSTRIDE + 4]);
            }
#pragma unroll
            for (int j = 0; j < 4; ++j) {
                const int base = (colbase + j * 8 + lq) * GSTRIDE + ks * 8 + lr;
                bf[j][0] = __float_as_uint(Bw[base]);
                bf[j][1] = __float_as_uint(Bw[base + 4]);
            }
#pragma unroll
            for (int i = 0; i < 4; ++i)
#pragma unroll
                for (int j = 0; j < 4; ++j)
                    mma_16x8x8(acc[i][j], af[i], bf[j]);
        }
        __syncthreads();
    }
#undef ISSUE

    // epilogue: rows m0+rowbase+i*16+lq(+8), cols n0+colbase+j*8+2lr(+1)
#pragma unroll
    for (int i = 0; i < 4; ++i) {
#pragma unroll
        for (int half = 0; half < 2; ++half) {
            const int m = m0 + rowbase + i * 16 + lq + half * 8;
            float* crow = C + (size_t)m * N;
            const float* arow = (MODE != 0) ? (aux + (size_t)m * N) : nullptr;
#pragma unroll
            for (int j = 0; j < 4; ++j) {
                const int n = n0 + colbase + j * 8 + 2 * lr;
                float v0 = acc[i][j][half * 2 + 0];
                float v1 = acc[i][j][half * 2 + 1];
                if (MODE == 0) {
                    if (bias) { v0 += bias[n]; v1 += bias[n + 1]; }
                } else if (MODE == 1) {
                    v0 += arow[n]; v1 += arow[n + 1];
                } else {
                    v0 = rndf(v0 / (1.f + __expf(-v0)) * arow[n]);
                    v1 = rndf(v1 / (1.f + __expf(-v1)) * arow[n + 1]);
                }
                float2 o2; o2.x = v0; o2.y = v1;
                *(float2*)(crow + n) = o2;
            }
        }
    }
}

// ---------------- RoPE on q (7 heads) and k (1 head) ----------------
__global__ void rope_kernel(float* __restrict__ qkv,
                            const float* __restrict__ cosT,
                            const float* __restrict__ sinT)
{
    const int row  = blockIdx.x;
    const int unit = blockIdx.y;
    const int d    = threadIdx.x;
    const int s    = row & (SEQ - 1);
    const float c  = cosT[s * DHEAD + d];
    const float sn = sinT[s * DHEAD + d];
    float* p = qkv + (size_t)row * QKV_N + (unit < NHEADS ? unit * DHEAD : HDIM);
    const float x1 = p[d], x2 = p[d + 64];
    p[d]      = x1 * c  - x2 * sn;
    p[d + 64] = x1 * sn + x2 * c;
}

// ---------------- causal flash attention (fp32 scalar, proven R4 version) ---
// Output rounded to tf32 (feeds the cp.async O-proj GEMM directly).
__global__ void __launch_bounds__(256) flash_kernel(const float* __restrict__ qkv,
                                                    float* __restrict__ out)
{
    extern __shared__ float sm[];
    float* Qs = sm;
    float* Ks = Qs + 64 * QSTRIDE;
    float* Vs = Ks + 64 * QSTRIDE;
    float* Ps = Vs + 64 * QSTRIDE;

    const int tid = threadIdx.x;
    const int tx = tid & 15, ty = tid >> 4;
    const int b = blockIdx.z, h = blockIdx.y;
    const int q0 = blockIdx.x * BQ;
    const float scale = 0.08838834764831845f;

    for (int f = tid; f < 64 * 32; f += 256) {
        const int r = f >> 5, c = (f & 31) << 2;
        float4 v = *(const float4*)(qkv + ((size_t)(b * SEQ + q0 + r)) * QKV_N + h * DHEAD + c);
        Qs[r * QSTRIDE + c]     = v.x * scale;
        Qs[r * QSTRIDE + c + 1] = v.y * scale;
        Qs[r * QSTRIDE + c + 2] = v.z * scale;
        Qs[r * QSTRIDE + c + 3] = v.w * scale;
    }

    float m_i[4], l_i[4], o[4][8];
#pragma unroll
    for (int i = 0; i < 4; i++) {
        m_i[i] = -1e30f; l_i[i] = 0.f;
#pragma unroll
        for (int j = 0; j < 8; j++) o[i][j] = 0.f;
    }

    const int jend = q0 / BK;
    for (int jt = 0; jt <= jend; ++jt) {
        __syncthreads();
        for (int f = tid; f < 64 * 32; f += 256) {
            const int r = f >> 5, c = (f & 31) << 2;
            const float* base = qkv + ((size_t)(b * SEQ + jt * BK + r)) * QKV_N;
            float4 kv = *(const float4*)(base + HDIM + c);
            Ks[r * QSTRIDE + c] = kv.x; Ks[r * QSTRIDE + c + 1] = kv.y;
            Ks[r * QSTRIDE + c + 2] = kv.z; Ks[r * QSTRIDE + c + 3] = kv.w;
            float4 vv = *(const float4*)(base + HDIM + DHEAD + c);
            Vs[r * QSTRIDE + c] = vv.x; Vs[r * QSTRIDE + c + 1] = vv.y;
            Vs[r * QSTRIDE + c + 2] = vv.z; Vs[r * QSTRIDE + c + 3] = vv.w;
        }
        __syncthreads();

        float s4[4][4];
#pragma unroll
        for (int i = 0; i < 4; i++)
#pragma unroll
            for (int j = 0; j < 4; j++) s4[i][j] = 0.f;

        for (int d = 0; d < 128; d += 4) {
            float4 qv[4], kv[4];
#pragma unroll
            for (int i = 0; i < 4; i++) qv[i] = *(const float4*)&Qs[(ty * 4 + i) * QSTRIDE + d];
#pragma unroll
            for (int j = 0; j < 4; j++) kv[j] = *(const float4*)&Ks[(tx + 16 * j) * QSTRIDE + d];
#pragma unroll
            for (int i = 0; i < 4; i++)
#pragma unroll
                for (int j = 0; j < 4; j++)
                    s4[i][j] += qv[i].x * kv[j].x + qv[i].y * kv[j].y
                              + qv[i].z * kv[j].z + qv[i].w * kv[j].w;
        }

        if (jt == jend) {
#pragma unroll
            for (int i = 0; i < 4; i++)
#pragma unroll
                for (int j = 0; j < 4; j++)
                    if (jt * BK + tx + 16 * j > q0 + ty * 4 + i) s4[i][j] = -1e30f;
        }

#pragma unroll
        for (int i = 0; i < 4; i++) {
            float rm = fmaxf(fmaxf(s4[i][0], s4[i][1]), fmaxf(s4[i][2], s4[i][3]));
#pragma unroll
            for (int off = 8; off >= 1; off >>= 1)
                rm = fmaxf(rm, __shfl_xor_sync(0xffffffffu, rm, off));
            const float mn = fmaxf(m_i[i], rm);
            const float alpha = __expf(m_i[i] - mn);
            m_i[i] = mn;
            float rs = 0.f;
#pragma unroll
            for (int j = 0; j < 4; j++) {
                const float p = __expf(s4[i][j] - mn);
                s4[i][j] = p; rs += p;
            }
#pragma unroll
            for (int off = 8; off >= 1; off >>= 1)
                rs += __shfl_xor_sync(0xffffffffu, rs, off);
            l_i[i] = l_i[i] * alpha + rs;
#pragma unroll
            for (int j = 0; j < 8; j++) o[i][j] *= alpha;
#pragma unroll
            for (int j = 0; j < 4; j++) Ps[(ty * 4 + i) * PSTRIDE + tx + 16 * j] = s4[i][j];
        }
        __syncthreads();

#pragma unroll 4
        for (int kk = 0; kk < 64; ++kk) {
            float pp[4];
#pragma unroll
            for (int i = 0; i < 4; i++) pp[i] = Ps[(ty * 4 + i) * PSTRIDE + kk];
            const float4 v0 = *(const float4*)&Vs[kk * QSTRIDE + tx * 8];
            const float4 v1 = *(const float4*)&Vs[kk * QSTRIDE + tx * 8 + 4];
            const float vv[8] = {v0.x, v0.y, v0.z, v0.w, v1.x, v1.y, v1.z, v1.w};
#pragma unroll
            for (int i = 0; i < 4; i++)
#pragma unroll
                for (int j = 0; j < 8; j++) o[i][j] = fmaf(pp[i], vv[j], o[i][j]);
        }
    }

#pragma unroll
    for (int i = 0; i < 4; i++) {
        const float invl = 1.f / l_i[i];
        const size_t orow = ((size_t)(b * SEQ + q0 + ty * 4 + i)) * HDIM + h * DHEAD + tx * 8;
#pragma unroll
        for (int j = 0; j < 8; j++) out[orow + j] = rndf(o[i][j] * invl);
    }
}

// ---------------- launcher ----------------
extern "C" void kernel_launch(void* const* d_in, const int* in_sizes, int n_in,
                              void* d_out, int out_size)
{
    int iwq, ibq, iwk, ibk, iwv, ibv, iwo, iwg, iwu, iwd, iln1, iln2, icos, isin;
    if (n_in >= 2 && in_sizes[1] == SEQ * SEQ) {
        icos = 2; isin = 3; iwq = 4; ibq = 5; iwk = 6; ibk = 7; iwv = 8; ibv = 9;
        iwo = 10; iwg = 11; iwu = 12; iwd = 13; iln1 = 14; iln2 = 15;
    } else {
        iwq = 1; ibq = 2; iwk = 3; ibk = 4; iwv = 5; ibv = 6; iwo = 7; iwg = 8;
        iwu = 9; iwd = 10; iln1 = 11; iln2 = 12; icos = 14; isin = 15;
    }

    const float* hs   = (const float*)d_in[0];
    const float* wq   = (const float*)d_in[iwq];
    const float* bq   = (const float*)d_in[ibq];
    const float* wk   = (const float*)d_in[iwk];
    const float* bk   = (const float*)d_in[ibk];
    const float* wv   = (const float*)d_in[iwv];
    const float* bv   = (const float*)d_in[ibv];
    const float* wo   = (const float*)d_in[iwo];
    const float* wg   = (const float*)d_in[iwg];
    const float* wu   = (const float*)d_in[iwu];
    const float* wd   = (const float*)d_in[iwd];
    const float* ln1  = (const float*)d_in[iln1];
    const float* ln2  = (const float*)d_in[iln2];
    const float* cosT = (const float*)d_in[icos];
    const float* sinT = (const float*)d_in[isin];

    float *p_h1, *p_qkv, *p_attn, *p_x2, *p_h2, *p_up, *p_wqkv, *p_bqkv, *p_wrnd;
    cudaGetSymbolAddress((void**)&p_h1,   g_h1);
    cudaGetSymbolAddress((void**)&p_qkv,  g_qkv);
    cudaGetSymbolAddress((void**)&p_attn, g_attn);
    cudaGetSymbolAddress((void**)&p_x2,   g_x2);
    cudaGetSymbolAddress((void**)&p_h2,   g_h2);
    cudaGetSymbolAddress((void**)&p_up,   g_up);
    cudaGetSymbolAddress((void**)&p_wqkv, g_wqkv);
    cudaGetSymbolAddress((void**)&p_bqkv, g_bqkv);
    cudaGetSymbolAddress((void**)&p_wrnd, g_wrnd);

    // concat wq|wk|wv and biases
    cudaMemcpyAsync(p_wqkv,                                 wq, (size_t)HDIM  * HDIM * 4, cudaMemcpyDeviceToDevice, 0);
    cudaMemcpyAsync(p_wqkv + (size_t)HDIM * HDIM,           wk, (size_t)DHEAD * HDIM * 4, cudaMemcpyDeviceToDevice, 0);
    cudaMemcpyAsync(p_wqkv + (size_t)(HDIM + DHEAD) * HDIM, wv, (size_t)DHEAD * HDIM * 4, cudaMemcpyDeviceToDevice, 0);
    cudaMemcpyAsync(p_bqkv,                bq, HDIM  * 4, cudaMemcpyDeviceToDevice, 0);
    cudaMemcpyAsync(p_bqkv + HDIM,         bk, DHEAD * 4, cudaMemcpyDeviceToDevice, 0);
    cudaMemcpyAsync(p_bqkv + HDIM + DHEAD, bv, DHEAD * 4, cudaMemcpyDeviceToDevice, 0);

    // pre-round all weights to tf32 (GEMMs then use raw cp.async)
    {
        int n4;
        n4 = QKV_N * HDIM / 4;
        round_tf32_kernel<<<(n4 + 255) / 256, 256>>>(p_wqkv, p_wqkv, n4);
        n4 = HDIM * HDIM / 4;
        round_tf32_kernel<<<(n4 + 255) / 256, 256>>>(wo, p_wrnd + WO_OFF, n4);
        n4 = IDIM * HDIM / 4;
        round_tf32_kernel<<<(n4 + 255) / 256, 256>>>(wg, p_wrnd + WG_OFF, n4);
        round_tf32_kernel<<<(n4 + 255) / 256, 256>>>(wu, p_wrnd + WU_OFF, n4);
        round_tf32_kernel<<<(n4 + 255) / 256, 256>>>(wd, p_wrnd + WD_OFF, n4);
    }

    const int smem_gemm = 3 * 2 * 128 * GSTRIDE * 4;   // 110592
    cudaFuncSetAttribute(gemm_ca<0>, cudaFuncAttributeMaxDynamicSharedMemorySize, smem_gemm);
    cudaFuncSetAttribute(gemm_ca<1>, cudaFuncAttributeMaxDynamicSharedMemorySize, smem_gemm);
    cudaFuncSetAttribute(gemm_ca<2>, cudaFuncAttributeMaxDynamicSharedMemorySize, smem_gemm);

    // 1) rmsnorm1 (tf32-rounded output)
    rmsnorm_kernel<<<M_ROWS, 256>>>(hs, ln1, p_h1);
    // 2) fused QKV projection
    gemm_ca<0><<<dim3(QKV_N / 128, M_ROWS / 128), 256, smem_gemm>>>(
        p_h1, p_wqkv, p_bqkv, nullptr, p_qkv, M_ROWS, QKV_N, HDIM);
    // 3) RoPE
    rope_kernel<<<dim3(M_ROWS, NHEADS + 1), 64>>>(p_qkv, cosT, sinT);
    // 4) scalar fp32 flash attention (proven; output tf32-rounded)
    const int flash_smem = (3 * 64 * QSTRIDE + 64 * PSTRIDE) * 4;
    cudaFuncSetAttribute(flash_kernel, cudaFuncAttributeMaxDynamicSharedMemorySize, flash_smem);
    flash_kernel<<<dim3(SEQ / BQ, NHEADS, 2), 256, flash_smem>>>(p_qkv, p_attn);
    // 5) O projection + residual
    gemm_ca<1><<<dim3(HDIM / 128, M_ROWS / 128), 256, smem_gemm>>>(
        p_attn, p_wrnd + WO_OFF, nullptr, hs, p_x2, M_ROWS, HDIM, HDIM);
    // 6) rmsnorm2
    rmsnorm_kernel<<<M_ROWS, 256>>>(p_x2, ln2, p_h2);
    // 7) up projection (raw output; consumed as fp32 aux)
    gemm_ca<0><<<dim3(IDIM / 128, M_ROWS / 128), 256, smem_gemm>>>(
        p_h2, p_wrnd + WU_OFF, nullptr, nullptr, p_up, M_ROWS, IDIM, HDIM);
    // 8) gate projection + fused silu(gate)*up (rounded; feeds down-proj)
    gemm_ca<2><<<dim3(IDIM / 128, M_ROWS / 128), 256, smem_gemm>>>(
        p_h2, p_wrnd + WG_OFF, nullptr, p_up, p_up, M_ROWS, IDIM, HDIM);
    // 9) down projection + residual -> output
    gemm_ca<1><<<dim3(HDIM / 128, M_ROWS / 128), 256, smem_gemm>>>(
        p_up, p_wrnd + WD_OFF, nullptr, p_x2, (float*)d_out, M_ROWS, HDIM, IDIM);
    (void)out_size;
}

// round 13
// speedup vs baseline: 2.6423x; 1.3466x over previous
#include <cuda_runtime.h>
#include <math.h>
#include <stdint.h>

// ---------------- problem constants ----------------
#define M_ROWS 4096      // B*S
#define HDIM   896
#define DHEAD  128
#define NHEADS 7
#define SEQ    2048
#define QKV_N  1152      // 7*128 + 128 + 128
#define IDIM   4864

#define GSTRIDE 36       // gemm smem stride (floats): bank = lane for fragment loads
#define FQS 132          // flash Q/K smem stride (132 mod 32 == 4 -> bank = lane, rows DON'T overlap)
#define FVS 132          // flash V smem stride
#define FPS 68           // flash P smem stride (68 mod 32 == 4 -> conflict-free A-frags)

// ---------------- scratch (device globals; no runtime alloc) ----------------
__device__ float g_h1  [M_ROWS * HDIM];
__device__ float g_qkv [M_ROWS * QKV_N];
__device__ float g_attn[M_ROWS * HDIM];
__device__ float g_x2  [M_ROWS * HDIM];
__device__ float g_h2  [M_ROWS * HDIM];
__device__ float g_up  [(size_t)M_ROWS * IDIM];
__device__ float g_wqkv[QKV_N * HDIM];
__device__ float g_bqkv[QKV_N];
// rounded weight copies: wo | wg | wu | wd
#define WO_OFF 0
#define WG_OFF (HDIM * HDIM)
#define WU_OFF (WG_OFF + IDIM * HDIM)
#define WD_OFF (WU_OFF + IDIM * HDIM)
#define WRND_TOTAL (WD_OFF + IDIM * HDIM)
__device__ float g_wrnd[WRND_TOTAL];

// ---------------- helpers ----------------
__device__ __forceinline__ uint32_t to_tf32(float f) {
    uint32_t r;
    asm("cvt.rna.tf32.f32 %0, %1;" : "=r"(r) : "f"(f));
    return r;
}
__device__ __forceinline__ float rndf(float f) { return __uint_as_float(to_tf32(f)); }
__device__ __forceinline__ void mma_16x8x8(float* c, const uint32_t* a, const uint32_t* b) {
    asm volatile(
        "mma.sync.aligned.m16n8k8.row.col.f32.tf32.tf32.f32 "
        "{%0,%1,%2,%3}, {%4,%5,%6,%7}, {%8,%9}, {%0,%1,%2,%3};"
        : "+f"(c[0]), "+f"(c[1]), "+f"(c[2]), "+f"(c[3])
        : "r"(a[0]), "r"(a[1]), "r"(a[2]), "r"(a[3]), "r"(b[0]), "r"(b[1]));
}
__device__ __forceinline__ uint32_t smem_u32(const void* p) {
    uint32_t a;
    asm("{ .reg .u64 t; cvta.to.shared.u64 t, %1; cvt.u32.u64 %0, t; }" : "=r"(a) : "l"(p));
    return a;
}
__device__ __forceinline__ void cp16(uint32_t dst, const float* src) {
    asm volatile("cp.async.cg.shared.global [%0], [%1], 16;" :: "r"(dst), "l"(src));
}

// ---------------- tf32 rounding kernel (weights) ----------------
__global__ void __launch_bounds__(256) round_tf32_kernel(const float* __restrict__ in,
                                                         float* __restrict__ out, int n4)
{
    const int i = blockIdx.x * 256 + threadIdx.x;
    if (i < n4) {
        float4 v = ((const float4*)in)[i];
        float4 o;
        o.x = rndf(v.x); o.y = rndf(v.y); o.z = rndf(v.z); o.w = rndf(v.w);
        ((float4*)out)[i] = o;
    }
}

// ---------------- RMSNorm (output rounded to tf32: pure GEMM input) --------
__global__ void __launch_bounds__(256) rmsnorm_kernel(const float* __restrict__ x,
                                                      const float* __restrict__ w,
                                                      float* __restrict__ out)
{
    __shared__ float red[256];
    const int row = blockIdx.x;
    const float* xr = x + (size_t)row * HDIM;
    float ss = 0.f;
    for (int i = threadIdx.x; i < HDIM; i += 256) { float v = xr[i]; ss += v * v; }
    red[threadIdx.x] = ss;
    __syncthreads();
    for (int s = 128; s > 0; s >>= 1) {
        if (threadIdx.x < s) red[threadIdx.x] += red[threadIdx.x + s];
        __syncthreads();
    }
    const float inv = rsqrtf(red[0] / (float)HDIM + 1e-6f);
    float* orow = out + (size_t)row * HDIM;
    for (int i = threadIdx.x; i < HDIM; i += 256) orow[i] = rndf(xr[i] * inv * w[i]);
}

// ---------------- tf32 mma GEMM, cp.async 3-stage: C = A @ B^T + epi -------
// Inputs A,B must already be tf32-rounded. 128x128 tile, 256 thr, BK=32.
// MODE 0: +bias[n] (nullable). MODE 1: +aux[m,n]. MODE 2: silu(acc)*aux -> rounded.
template<int MODE>
__global__ void __launch_bounds__(256) gemm_ca(const float* __restrict__ A,
                                               const float* __restrict__ B,
                                               const float* __restrict__ bias,
                                               const float* __restrict__ aux,
                                               float* __restrict__ C,
                                               int M, int N, int K)
{
    extern __shared__ float sm[];
    const uint32_t sbase = smem_u32(sm);
    constexpr uint32_t STG = 2 * 128 * GSTRIDE;   // floats per stage (A+B)

    const int tid = threadIdx.x;
    const int wid = tid >> 5, lane = tid & 31;
    const int lq = lane >> 2, lr = lane & 3;
    const int warp_m = wid >> 2, warp_n = wid & 3;
    const int rowbase = warp_m * 64, colbase = warp_n * 32;
    const int m0 = blockIdx.y * 128, n0 = blockIdx.x * 128;

    const int pr = tid >> 3;          // 0..31
    const int pc = (tid & 7) << 2;    // 0..28

    float acc[4][4][4];
#pragma unroll
    for (int i = 0; i < 4; i++)
#pragma unroll
        for (int j = 0; j < 4; j++)
#pragma unroll
            for (int q = 0; q < 4; q++) acc[i][j][q] = 0.f;

    const int nch = K >> 5;
    const float* Abase = A + (size_t)m0 * K;
    const float* Bbase = B + (size_t)n0 * K;

#define ISSUE(CH, S) do { \
        const float* Ap_ = Abase + (CH) * 32; \
        const float* Bp_ = Bbase + (CH) * 32; \
        const uint32_t sA_ = sbase + (S) * STG * 4; \
        const uint32_t sB_ = sA_ + 128 * GSTRIDE * 4; \
        _Pragma("unroll") \
        for (int p_ = 0; p_ < 4; ++p_) { \
            const int r_ = pr + p_ * 32; \
            cp16(sA_ + (uint32_t)(r_ * GSTRIDE + pc) * 4, Ap_ + (size_t)r_ * K + pc); \
            cp16(sB_ + (uint32_t)(r_ * GSTRIDE + pc) * 4, Bp_ + (size_t)r_ * K + pc); \
        } \
    } while (0)

    // prologue: stages 0,1
    ISSUE(0, 0);
    asm volatile("cp.async.commit_group;");
    if (nch > 1) ISSUE(1, 1);
    asm volatile("cp.async.commit_group;");

    for (int ch = 0; ch < nch; ++ch) {
        if (ch + 2 < nch) ISSUE(ch + 2, (ch + 2) % 3);
        asm volatile("cp.async.commit_group;");
        asm volatile("cp.async.wait_group 2;");
        __syncthreads();

        const float* Aw = sm + (ch % 3) * STG;
        const float* Bw = Aw + 128 * GSTRIDE;
#pragma unroll
        for (int ks = 0; ks < 4; ++ks) {
            uint32_t af[4][4], bf[4][2];
#pragma unroll
            for (int i = 0; i < 4; ++i) {
                const int base = (rowbase + i * 16 + lq) * GSTRIDE + ks * 8 + lr;
                af[i][0] = __float_as_uint(Aw[base]);
                af[i][1] = __float_as_uint(Aw[base + 8 * GSTRIDE]);
                af[i][2] = __float_as_uint(Aw[base + 4]);
                af[i][3] = __float_as_uint(Aw[base + 8 * GSTRIDE + 4]);
            }
#pragma unroll
            for (int j = 0; j < 4; ++j) {
                const int base = (colbase + j * 8 + lq) * GSTRIDE + ks * 8 + lr;
                bf[j][0] = __float_as_uint(Bw[base]);
                bf[j][1] = __float_as_uint(Bw[base + 4]);
            }
#pragma unroll
            for (int i = 0; i < 4; ++i)
#pragma unroll
                for (int j = 0; j < 4; ++j)
                    mma_16x8x8(acc[i][j], af[i], bf[j]);
        }
        __syncthreads();
    }
#undef ISSUE

    // epilogue: rows m0+rowbase+i*16+lq(+8), cols n0+colbase+j*8+2lr(+1)
#pragma unroll
    for (int i = 0; i < 4; ++i) {
#pragma unroll
        for (int half = 0; half < 2; ++half) {
            const int m = m0 + rowbase + i * 16 + lq + half * 8;
            float* crow = C + (size_t)m * N;
            const float* arow = (MODE != 0) ? (aux + (size_t)m * N) : nullptr;
#pragma unroll
            for (int j = 0; j < 4; ++j) {
                const int n = n0 + colbase + j * 8 + 2 * lr;
                float v0 = acc[i][j][half * 2 + 0];
                float v1 = acc[i][j][half * 2 + 1];
                if (MODE == 0) {
                    if (bias) { v0 += bias[n]; v1 += bias[n + 1]; }
                } else if (MODE == 1) {
                    v0 += arow[n]; v1 += arow[n + 1];
                } else {
                    v0 = rndf(v0 / (1.f + __expf(-v0)) * arow[n]);
                    v1 = rndf(v1 / (1.f + __expf(-v1)) * arow[n + 1]);
                }
                float2 o2; o2.x = v0; o2.y = v1;
                *(float2*)(crow + n) = o2;
            }
        }
    }
}

// ---------------- RoPE on q (7 heads) and k (1 head) ----------------
__global__ void rope_kernel(float* __restrict__ qkv,
                            const float* __restrict__ cosT,
                            const float* __restrict__ sinT)
{
    const int row  = blockIdx.x;
    const int unit = blockIdx.y;
    const int d    = threadIdx.x;
    const int s    = row & (SEQ - 1);
    const float c  = cosT[s * DHEAD + d];
    const float sn = sinT[s * DHEAD + d];
    float* p = qkv + (size_t)row * QKV_N + (unit < NHEADS ? unit * DHEAD : HDIM);
    const float x1 = p[d], x2 = p[d + 64];
    p[d]      = x1 * c  - x2 * sn;
    p[d + 64] = x1 * sn + x2 * c;
}

// ---------------- tensor-core causal flash attention (tf32 mma) -------------
// BQ=128 q rows per CTA, BK=64 keys per tile, 8 warps x 16 q-rows.
__global__ void __launch_bounds__(256) flash_mma_kernel(const float* __restrict__ qkv,
                                                        float* __restrict__ out)
{
    extern __shared__ float sm[];
    float* Qs = sm;                     // 128 x FQS(132)
    float* Ks = Qs + 128 * FQS;         // 64 x FQS(132)
    float* Vs = Ks + 64 * FQS;          // 64 x FVS(132)
    float* Ps = Vs + 64 * FVS;          // 128 x FPS(68)

    const int tid = threadIdx.x;
    const int wid = tid >> 5, lane = tid & 31;
    const int lq = lane >> 2, lr = lane & 3;
    const int b = blockIdx.z, h = blockIdx.y;
    const int q0 = ((int)gridDim.x - 1 - (int)blockIdx.x) * 128;   // heavy tiles first
    const float scale = 0.08838834764831845f;   // 1/sqrt(128)

    // load + scale + round Q tile (128 x 128)
#pragma unroll
    for (int p = 0; p < 16; ++p) {
        const int f = tid + p * 256;
        const int r = f >> 5, c = (f & 31) << 2;
        float4 v = *(const float4*)(qkv + ((size_t)(b * SEQ + q0 + r)) * QKV_N + h * DHEAD + c);
        float4 o;
        o.x = rndf(v.x * scale); o.y = rndf(v.y * scale);
        o.z = rndf(v.z * scale); o.w = rndf(v.w * scale);
        *(float4*)&Qs[r * FQS + c] = o;
    }

    float oacc[16][4];
#pragma unroll
    for (int nf = 0; nf < 16; ++nf)
#pragma unroll
        for (int q = 0; q < 4; ++q) oacc[nf][q] = 0.f;
    float m0v = -1e30f, m1v = -1e30f, l0v = 0.f, l1v = 0.f;

    const int ntiles = q0 / 64 + 2;
    for (int jt = 0; jt < ntiles; ++jt) {
        __syncthreads();   // previous tile's K/V reads done (also fences Qs on jt=0)
        // load + round K,V tiles (64 x 128 each)
#pragma unroll
        for (int p = 0; p < 8; ++p) {
            const int f = tid + p * 256;
            const int r = f >> 5, c = (f & 31) << 2;
            const float* base = qkv + ((size_t)(b * SEQ + jt * 64 + r)) * QKV_N;
            float4 kv = *(const float4*)(base + HDIM + c);
            float4 ok;
            ok.x = rndf(kv.x); ok.y = rndf(kv.y); ok.z = rndf(kv.z); ok.w = rndf(kv.w);
            *(float4*)&Ks[r * FQS + c] = ok;
            float4 vv = *(const float4*)(base + HDIM + DHEAD + c);
            float4 ov;
            ov.x = rndf(vv.x); ov.y = rndf(vv.y); ov.z = rndf(vv.z); ov.w = rndf(vv.w);
            *(float4*)&Vs[r * FVS + c] = ov;
        }
        __syncthreads();

        // ---- S = Q @ K^T : warp rows 16*wid.., all 64 cols ----
        float sacc[8][4];
#pragma unroll
        for (int f = 0; f < 8; ++f)
#pragma unroll
            for (int q = 0; q < 4; ++q) sacc[f][q] = 0.f;

#pragma unroll
        for (int ks = 0; ks < 16; ++ks) {
            uint32_t af[4];
            const int abase = (wid * 16 + lq) * FQS + ks * 8 + lr;
            af[0] = __float_as_uint(Qs[abase]);
            af[1] = __float_as_uint(Qs[abase + 8 * FQS]);
            af[2] = __float_as_uint(Qs[abase + 4]);
            af[3] = __float_as_uint(Qs[abase + 8 * FQS + 4]);
#pragma unroll
            for (int f = 0; f < 8; ++f) {
                uint32_t bf[2];
                const int bbase = (f * 8 + lq) * FQS + ks * 8 + lr;
                bf[0] = __float_as_uint(Ks[bbase]);
                bf[1] = __float_as_uint(Ks[bbase + 4]);
                mma_16x8x8(sacc[f], af, bf);
            }
        }

        // causal mask (only final two tiles can intersect the diagonal)
        if (jt * 64 + 63 > q0) {
            const int r0 = q0 + wid * 16 + lq;
#pragma unroll
            for (int f = 0; f < 8; ++f) {
                const int c0 = jt * 64 + f * 8 + 2 * lr;
                if (c0 > r0)     sacc[f][0] = -1e30f;
                if (c0 + 1 > r0) sacc[f][1] = -1e30f;
                if (c0 > r0 + 8)     sacc[f][2] = -1e30f;
                if (c0 + 1 > r0 + 8) sacc[f][3] = -1e30f;
            }
        }

        // ---- online softmax (rows lq / lq+8, reduce across lr quad) ----
        float mx0 = -1e30f, mx1 = -1e30f;
#pragma unroll
        for (int f = 0; f < 8; ++f) {
            mx0 = fmaxf(mx0, fmaxf(sacc[f][0], sacc[f][1]));
            mx1 = fmaxf(mx1, fmaxf(sacc[f][2], sacc[f][3]));
        }
        mx0 = fmaxf(mx0, __shfl_xor_sync(0xffffffffu, mx0, 1));
        mx0 = fmaxf(mx0, __shfl_xor_sync(0xffffffffu, mx0, 2));
        mx1 = fmaxf(mx1, __shfl_xor_sync(0xffffffffu, mx1, 1));
        mx1 = fmaxf(mx1, __shfl_xor_sync(0xffffffffu, mx1, 2));

        const float mn0 = fmaxf(m0v, mx0), mn1 = fmaxf(m1v, mx1);
        const float a0 = __expf(m0v - mn0), a1 = __expf(m1v - mn1);
        m0v = mn0; m1v = mn1;

        float s0 = 0.f, s1 = 0.f;
#pragma unroll
        for (int f = 0; f < 8; ++f) {
            sacc[f][0] = __expf(sacc[f][0] - mn0);
            sacc[f][1] = __expf(sacc[f][1] - mn0);
            sacc[f][2] = __expf(sacc[f][2] - mn1);
            sacc[f][3] = __expf(sacc[f][3] - mn1);
            s0 += sacc[f][0] + sacc[f][1];
            s1 += sacc[f][2] + sacc[f][3];
        }
        s0 += __shfl_xor_sync(0xffffffffu, s0, 1);
        s0 += __shfl_xor_sync(0xffffffffu, s0, 2);
        s1 += __shfl_xor_sync(0xffffffffu, s1, 1);
        s1 += __shfl_xor_sync(0xffffffffu, s1, 2);
        l0v = l0v * a0 + s0;
        l1v = l1v * a1 + s1;
#pragma unroll
        for (int nf = 0; nf < 16; ++nf) {
            oacc[nf][0] *= a0; oacc[nf][1] *= a0;
            oacc[nf][2] *= a1; oacc[nf][3] *= a1;
        }

        // store P fragments (warp-local region of Ps)
#pragma unroll
        for (int f = 0; f < 8; ++f) {
            float2 p0; p0.x = rndf(sacc[f][0]); p0.y = rndf(sacc[f][1]);
            *(float2*)&Ps[(wid * 16 + lq) * FPS + f * 8 + 2 * lr] = p0;
            float2 p1; p1.x = rndf(sacc[f][2]); p1.y = rndf(sacc[f][3]);
            *(float2*)&Ps[(wid * 16 + lq + 8) * FPS + f * 8 + 2 * lr] = p1;
        }
        __syncwarp();

        // ---- O += P @ V ----
#pragma unroll
        for (int ks = 0; ks < 8; ++ks) {
            uint32_t pa[4];
            const int pbase = (wid * 16 + lq) * FPS + ks * 8 + lr;
            pa[0] = __float_as_uint(Ps[pbase]);
            pa[1] = __float_as_uint(Ps[pbase + 8 * FPS]);
            pa[2] = __float_as_uint(Ps[pbase + 4]);
            pa[3] = __float_as_uint(Ps[pbase + 8 * FPS + 4]);
#pragma unroll
            for (int nf = 0; nf < 16; ++nf) {
                uint32_t vb[2];
                const int vbase = (ks * 8 + lr) * FVS + nf * 8 + lq;
                vb[0] = __float_as_uint(Vs[vbase]);
                vb[1] = __float_as_uint(Vs[vbase + 4 * FVS]);
                mma_16x8x8(oacc[nf], pa, vb);
            }
        }
    }

    // epilogue: O /= l, round (pure O-proj GEMM input), write packed layout
    const float inv0 = 1.f / l0v, inv1 = 1.f / l1v;
    const int r0 = q0 + wid * 16 + lq;
#pragma unroll
    for (int nf = 0; nf < 16; ++nf) {
        const int col = h * DHEAD + nf * 8 + 2 * lr;
        float2 o0; o0.x = rndf(oacc[nf][0] * inv0); o0.y = rndf(oacc[nf][1] * inv0);
        *(float2*)(out + ((size_t)(b * SEQ + r0)) * HDIM + col) = o0;
        float2 o1; o1.x = rndf(oacc[nf][2] * inv1); o1.y = rndf(oacc[nf][3] * inv1);
        *(float2*)(out + ((size_t)(b * SEQ + r0 + 8)) * HDIM + col) = o1;
    }
}

// ---------------- launcher ----------------
extern "C" void kernel_launch(void* const* d_in, const int* in_sizes, int n_in,
                              void* d_out, int out_size)
{
    int iwq, ibq, iwk, ibk, iwv, ibv, iwo, iwg, iwu, iwd, iln1, iln2, icos, isin;
    if (n_in >= 2 && in_sizes[1] == SEQ * SEQ) {
        icos = 2; isin = 3; iwq = 4; ibq = 5; iwk = 6; ibk = 7; iwv = 8; ibv = 9;
        iwo = 10; iwg = 11; iwu = 12; iwd = 13; iln1 = 14; iln2 = 15;
    } else {
        iwq = 1; ibq = 2; iwk = 3; ibk = 4; iwv = 5; ibv = 6; iwo = 7; iwg = 8;
        iwu = 9; iwd = 10; iln1 = 11; iln2 = 12; icos = 14; isin = 15;
    }

    const float* hs   = (const float*)d_in[0];
    const float* wq   = (const float*)d_in[iwq];
    const float* bq   = (const float*)d_in[ibq];
    const float* wk   = (const float*)d_in[iwk];
    const float* bk   = (const float*)d_in[ibk];
    const float* wv   = (const float*)d_in[iwv];
    const float* bv   = (const float*)d_in[ibv];
    const float* wo   = (const float*)d_in[iwo];
    const float* wg   = (const float*)d_in[iwg];
    const float* wu   = (const float*)d_in[iwu];
    const float* wd   = (const float*)d_in[iwd];
    const float* ln1  = (const float*)d_in[iln1];
    const float* ln2  = (const float*)d_in[iln2];
    const float* cosT = (const float*)d_in[icos];
    const float* sinT = (const float*)d_in[isin];

    float *p_h1, *p_qkv, *p_attn, *p_x2, *p_h2, *p_up, *p_wqkv, *p_bqkv, *p_wrnd;
    cudaGetSymbolAddress((void**)&p_h1,   g_h1);
    cudaGetSymbolAddress((void**)&p_qkv,  g_qkv);
    cudaGetSymbolAddress((void**)&p_attn, g_attn);
    cudaGetSymbolAddress((void**)&p_x2,   g_x2);
    cudaGetSymbolAddress((void**)&p_h2,   g_h2);
    cudaGetSymbolAddress((void**)&p_up,   g_up);
    cudaGetSymbolAddress((void**)&p_wqkv, g_wqkv);
    cudaGetSymbolAddress((void**)&p_bqkv, g_bqkv);
    cudaGetSymbolAddress((void**)&p_wrnd, g_wrnd);

    // concat wq|wk|wv and biases
    cudaMemcpyAsync(p_wqkv,                                 wq, (size_t)HDIM  * HDIM * 4, cudaMemcpyDeviceToDevice, 0);
    cudaMemcpyAsync(p_wqkv + (size_t)HDIM * HDIM,           wk, (size_t)DHEAD * HDIM * 4, cudaMemcpyDeviceToDevice, 0);
    cudaMemcpyAsync(p_wqkv + (size_t)(HDIM + DHEAD) * HDIM, wv, (size_t)DHEAD * HDIM * 4, cudaMemcpyDeviceToDevice, 0);
    cudaMemcpyAsync(p_bqkv,                bq, HDIM  * 4, cudaMemcpyDeviceToDevice, 0);
    cudaMemcpyAsync(p_bqkv + HDIM,         bk, DHEAD * 4, cudaMemcpyDeviceToDevice, 0);
    cudaMemcpyAsync(p_bqkv + HDIM + DHEAD, bv, DHEAD * 4, cudaMemcpyDeviceToDevice, 0);

    // pre-round all weights to tf32 (GEMMs then use raw cp.async)
    {
        int n4;
        n4 = QKV_N * HDIM / 4;
        round_tf32_kernel<<<(n4 + 255) / 256, 256>>>(p_wqkv, p_wqkv, n4);
        n4 = HDIM * HDIM / 4;
        round_tf32_kernel<<<(n4 + 255) / 256, 256>>>(wo, p_wrnd + WO_OFF, n4);
        n4 = IDIM * HDIM / 4;
        round_tf32_kernel<<<(n4 + 255) / 256, 256>>>(wg, p_wrnd + WG_OFF, n4);
        round_tf32_kernel<<<(n4 + 255) / 256, 256>>>(wu, p_wrnd + WU_OFF, n4);
        round_tf32_kernel<<<(n4 + 255) / 256, 256>>>(wd, p_wrnd + WD_OFF, n4);
    }

    const int smem_gemm = 3 * 2 * 128 * GSTRIDE * 4;   // 110592
    cudaFuncSetAttribute(gemm_ca<0>, cudaFuncAttributeMaxDynamicSharedMemorySize, smem_gemm);
    cudaFuncSetAttribute(gemm_ca<1>, cudaFuncAttributeMaxDynamicSharedMemorySize, smem_gemm);
    cudaFuncSetAttribute(gemm_ca<2>, cudaFuncAttributeMaxDynamicSharedMemorySize, smem_gemm);
    const int smem_flash = (128 * FQS + 64 * FQS + 64 * FVS + 128 * FPS) * 4;   // 169984
    cudaFuncSetAttribute(flash_mma_kernel, cudaFuncAttributeMaxDynamicSharedMemorySize, smem_flash);

    // 1) rmsnorm1 (tf32-rounded output)
    rmsnorm_kernel<<<M_ROWS, 256>>>(hs, ln1, p_h1);
    // 2) fused QKV projection
    gemm_ca<0><<<dim3(QKV_N / 128, M_ROWS / 128), 256, smem_gemm>>>(
        p_h1, p_wqkv, p_bqkv, nullptr, p_qkv, M_ROWS, QKV_N, HDIM);
    // 3) RoPE
    rope_kernel<<<dim3(M_ROWS, NHEADS + 1), 64>>>(p_qkv, cosT, sinT);
    // 4) tensor-core flash attention (rounds its own inputs/outputs)
    flash_mma_kernel<<<dim3(SEQ / 128, NHEADS, 2), 256, smem_flash>>>(p_qkv, p_attn);
    // 5) O projection + residual
    gemm_ca<1><<<dim3(HDIM / 128, M_ROWS / 128), 256, smem_gemm>>>(
        p_attn, p_wrnd + WO_OFF, nullptr, hs, p_x2, M_ROWS, HDIM, HDIM);
    // 6) rmsnorm2
    rmsnorm_kernel<<<M_ROWS, 256>>>(p_x2, ln2, p_h2);
    // 7) up projection (raw output; consumed as fp32 aux)
    gemm_ca<0><<<dim3(IDIM / 128, M_ROWS / 128), 256, smem_gemm>>>(
        p_h2, p_wrnd + WU_OFF, nullptr, nullptr, p_up, M_ROWS, IDIM, HDIM);
    // 8) gate projection + fused silu(gate)*up (rounded; feeds down-proj)
    gemm_ca<2><<<dim3(IDIM / 128, M_ROWS / 128), 256, smem_gemm>>>(
        p_h2, p_wrnd + WG_OFF, nullptr, p_up, p_up, M_ROWS, IDIM, HDIM);
    // 9) down projection + residual -> output
    gemm_ca<1><<<dim3(HDIM / 128, M_ROWS / 128), 256, smem_gemm>>>(
        p_up, p_wrnd + WD_OFF, nullptr, p_x2, (float*)d_out, M_ROWS, HDIM, IDIM);
    (void)out_size;
}

// round 14
// speedup vs baseline: 4.3882x; 1.6607x over previous
#include <cuda_runtime.h>
#include <cuda_fp16.h>
#include <math.h>
#include <stdint.h>

// ---------------- problem constants ----------------
#define M_ROWS 4096      // B*S
#define HDIM   896
#define DHEAD  128
#define NHEADS 7
#define SEQ    2048
#define QKV_N  1152      // 7*128 + 128 + 128
#define IDIM   4864

#define GSTRIDE 36       // gemm smem stride (32-bit words): bank = lane for fragment loads
#define FQW 68           // flash Q/K smem stride in words (68 mod 32 == 4 -> bank = lane)
#define FVS 132          // flash V smem stride (floats)
#define FPS 68           // flash P smem stride (floats)

// ---------------- scratch (device globals; no runtime alloc) ----------------
__device__ float  g_qkv [M_ROWS * QKV_N];
__device__ float  g_x2  [M_ROWS * HDIM];
__device__ float  g_up  [(size_t)M_ROWS * IDIM];
__device__ __half g_h1h [M_ROWS * HDIM];
__device__ __half g_h2h [M_ROWS * HDIM];
__device__ __half g_attnh[M_ROWS * HDIM];
__device__ __half g_gah [(size_t)M_ROWS * IDIM];
__device__ __half g_wqkvh[QKV_N * HDIM];
__device__ float  g_bqkv[QKV_N];
// half weight copies: wo | wg | wu | wd
#define WO_OFF 0
#define WG_OFF (HDIM * HDIM)
#define WU_OFF (WG_OFF + IDIM * HDIM)
#define WD_OFF (WU_OFF + IDIM * HDIM)
#define WRND_TOTAL (WD_OFF + IDIM * HDIM)
__device__ __half g_wh[WRND_TOTAL];

// ---------------- helpers ----------------
__device__ __forceinline__ uint32_t to_tf32(float f) {
    uint32_t r;
    asm("cvt.rna.tf32.f32 %0, %1;" : "=r"(r) : "f"(f));
    return r;
}
__device__ __forceinline__ float rndf(float f) { return __uint_as_float(to_tf32(f)); }
__device__ __forceinline__ uint32_t pack2h(float a, float b) {
    __half2 h = __floats2half2_rn(a, b);
    return *(uint32_t*)&h;
}
// fp16 mma: D(f32) += A(f16) @ B(f16)
__device__ __forceinline__ void mma_f16(float* c, const uint32_t* a, const uint32_t* b) {
    asm volatile(
        "mma.sync.aligned.m16n8k16.row.col.f32.f16.f16.f32 "
        "{%0,%1,%2,%3}, {%4,%5,%6,%7}, {%8,%9}, {%0,%1,%2,%3};"
        : "+f"(c[0]), "+f"(c[1]), "+f"(c[2]), "+f"(c[3])
        : "r"(a[0]), "r"(a[1]), "r"(a[2]), "r"(a[3]), "r"(b[0]), "r"(b[1]));
}
// tf32 mma (flash P@V only)
__device__ __forceinline__ void mma_tf32(float* c, const uint32_t* a, const uint32_t* b) {
    asm volatile(
        "mma.sync.aligned.m16n8k8.row.col.f32.tf32.tf32.f32 "
        "{%0,%1,%2,%3}, {%4,%5,%6,%7}, {%8,%9}, {%0,%1,%2,%3};"
        : "+f"(c[0]), "+f"(c[1]), "+f"(c[2]), "+f"(c[3])
        : "r"(a[0]), "r"(a[1]), "r"(a[2]), "r"(a[3]), "r"(b[0]), "r"(b[1]));
}
__device__ __forceinline__ uint32_t smem_u32(const void* p) {
    uint32_t a;
    asm("{ .reg .u64 t; cvta.to.shared.u64 t, %1; cvt.u32.u64 %0, t; }" : "=r"(a) : "l"(p));
    return a;
}
__device__ __forceinline__ void cp16(uint32_t dst, const void* src) {
    asm volatile("cp.async.cg.shared.global [%0], [%1], 16;" :: "r"(dst), "l"(src));
}

// ---------------- fp32 -> fp16 weight conversion ----------------
__global__ void __launch_bounds__(256) cvt_h_kernel(const float* __restrict__ in,
                                                    __half* __restrict__ out, int n4)
{
    const int i = blockIdx.x * 256 + threadIdx.x;
    if (i < n4) {
        float4 v = ((const float4*)in)[i];
        uint2 o;
        o.x = pack2h(v.x, v.y);
        o.y = pack2h(v.z, v.w);
        ((uint2*)out)[i] = o;
    }
}

// ---------------- RMSNorm (fp16 output: pure GEMM A operand) ----------------
__global__ void __launch_bounds__(256) rmsnorm_kernel(const float* __restrict__ x,
                                                      const float* __restrict__ w,
                                                      __half* __restrict__ out)
{
    __shared__ float red[256];
    const int row = blockIdx.x;
    const float* xr = x + (size_t)row * HDIM;
    float ss = 0.f;
    for (int i = threadIdx.x; i < HDIM; i += 256) { float v = xr[i]; ss += v * v; }
    red[threadIdx.x] = ss;
    __syncthreads();
    for (int s = 128; s > 0; s >>= 1) {
        if (threadIdx.x < s) red[threadIdx.x] += red[threadIdx.x + s];
        __syncthreads();
    }
    const float inv = rsqrtf(red[0] / (float)HDIM + 1e-6f);
    __half* orow = out + (size_t)row * HDIM;
    for (int i = threadIdx.x; i < HDIM; i += 256)
        orow[i] = __float2half_rn(xr[i] * inv * w[i]);
}

// ---------------- fp16 mma GEMM, cp.async 3-stage: C = A @ B^T + epi -------
// A,B half (K-major). 128x128 tile, 256 thr, k-chunk = 64 halves (32 words).
// MODE 0: +bias[n] fp32 out. MODE 1: +aux[m,n] fp32 out. MODE 2: silu(acc)*aux -> HALF out.
template<int MODE>
__global__ void __launch_bounds__(256) gemm_h(const __half* __restrict__ A,
                                              const __half* __restrict__ B,
                                              const float* __restrict__ bias,
                                              const float* __restrict__ aux,
                                              float* __restrict__ C,
                                              int M, int N, int K)
{
    extern __shared__ float sm[];
    const uint32_t sbase = smem_u32(sm);
    constexpr uint32_t STG = 2 * 128 * GSTRIDE;   // words per stage (A+B)

    const int tid = threadIdx.x;
    const int wid = tid >> 5, lane = tid & 31;
    const int lq = lane >> 2, lr = lane & 3;
    const int warp_m = wid >> 2, warp_n = wid & 3;
    const int rowbase = warp_m * 64, colbase = warp_n * 32;
    const int m0 = blockIdx.y * 128, n0 = blockIdx.x * 128;

    const int pr = tid >> 3;          // 0..31 (row step 32)
    const int pc = (tid & 7) << 2;    // word col 0..28 (16B per thread)

    float acc[4][4][4];
#pragma unroll
    for (int i = 0; i < 4; i++)
#pragma unroll
        for (int j = 0; j < 4; j++)
#pragma unroll
            for (int q = 0; q < 4; q++) acc[i][j][q] = 0.f;

    const int nch = K >> 6;           // 64 halves per chunk
    const __half* Abase = A + (size_t)m0 * K;
    const __half* Bbase = B + (size_t)n0 * K;

#define ISSUE(CH, S) do { \
        const __half* Ap_ = Abase + (CH) * 64; \
        const __half* Bp_ = Bbase + (CH) * 64; \
        const uint32_t sA_ = sbase + (S) * STG * 4; \
        const uint32_t sB_ = sA_ + 128 * GSTRIDE * 4; \
        _Pragma("unroll") \
        for (int p_ = 0; p_ < 4; ++p_) { \
            const int r_ = pr + p_ * 32; \
            cp16(sA_ + (uint32_t)(r_ * GSTRIDE + pc) * 4, Ap_ + (size_t)r_ * K + pc * 2); \
            cp16(sB_ + (uint32_t)(r_ * GSTRIDE + pc) * 4, Bp_ + (size_t)r_ * K + pc * 2); \
        } \
    } while (0)

    // prologue: stages 0,1
    ISSUE(0, 0);
    asm volatile("cp.async.commit_group;");
    if (nch > 1) ISSUE(1, 1);
    asm volatile("cp.async.commit_group;");

    for (int ch = 0; ch < nch; ++ch) {
        if (ch + 1 < nch) asm volatile("cp.async.wait_group 1;");
        else              asm volatile("cp.async.wait_group 0;");
        __syncthreads();
        // issue AFTER the barrier: stage (ch+2)%3 readers (iter ch-1) are provably done
        if (ch + 2 < nch) {
            ISSUE(ch + 2, (ch + 2) % 3);
            asm volatile("cp.async.commit_group;");
        }

        const float* Aw = sm + (ch % 3) * STG;
        const float* Bw = Aw + 128 * GSTRIDE;
#pragma unroll
        for (int ks = 0; ks < 4; ++ks) {    // 4 x k16
            uint32_t af[4][4], bf[4][2];
#pragma unroll
            for (int i = 0; i < 4; ++i) {
                const int base = (rowbase + i * 16 + lq) * GSTRIDE + ks * 8 + lr;
                af[i][0] = __float_as_uint(Aw[base]);
                af[i][1] = __float_as_uint(Aw[base + 8 * GSTRIDE]);
                af[i][2] = __float_as_uint(Aw[base + 4]);
                af[i][3] = __float_as_uint(Aw[base + 8 * GSTRIDE + 4]);
            }
#pragma unroll
            for (int j = 0; j < 4; ++j) {
                const int base = (colbase + j * 8 + lq) * GSTRIDE + ks * 8 + lr;
                bf[j][0] = __float_as_uint(Bw[base]);
                bf[j][1] = __float_as_uint(Bw[base + 4]);
            }
#pragma unroll
            for (int i = 0; i < 4; ++i)
#pragma unroll
                for (int j = 0; j < 4; ++j)
                    mma_f16(acc[i][j], af[i], bf[j]);
        }
        __syncthreads();   // readers done before next iter's ISSUE overwrites this stage
    }
#undef ISSUE

    // epilogue
#pragma unroll
    for (int i = 0; i < 4; ++i) {
#pragma unroll
        for (int half_ = 0; half_ < 2; ++half_) {
            const int m = m0 + rowbase + i * 16 + lq + half_ * 8;
            const float* arow = (MODE != 0) ? (aux + (size_t)m * N) : nullptr;
#pragma unroll
            for (int j = 0; j < 4; ++j) {
                const int n = n0 + colbase + j * 8 + 2 * lr;
                float v0 = acc[i][j][half_ * 2 + 0];
                float v1 = acc[i][j][half_ * 2 + 1];
                if (MODE == 0) {
                    if (bias) { v0 += bias[n]; v1 += bias[n + 1]; }
                    *(float2*)(C + (size_t)m * N + n) = make_float2(v0, v1);
                } else if (MODE == 1) {
                    v0 += arow[n]; v1 += arow[n + 1];
                    *(float2*)(C + (size_t)m * N + n) = make_float2(v0, v1);
                } else {
                    v0 = v0 / (1.f + __expf(-v0)) * arow[n];
                    v1 = v1 / (1.f + __expf(-v1)) * arow[n + 1];
                    *(uint32_t*)((__half*)C + (size_t)m * N + n) = pack2h(v0, v1);
                }
            }
        }
    }
}

// ---------------- RoPE on q (7 heads) and k (1 head) ----------------
__global__ void rope_kernel(float* __restrict__ qkv,
                            const float* __restrict__ cosT,
                            const float* __restrict__ sinT)
{
    const int row  = blockIdx.x;
    const int unit = blockIdx.y;
    const int d    = threadIdx.x;
    const int s    = row & (SEQ - 1);
    const float c  = cosT[s * DHEAD + d];
    const float sn = sinT[s * DHEAD + d];
    float* p = qkv + (size_t)row * QKV_N + (unit < NHEADS ? unit * DHEAD : HDIM);
    const float x1 = p[d], x2 = p[d + 64];
    p[d]      = x1 * c  - x2 * sn;
    p[d + 64] = x1 * sn + x2 * c;
}

// ---------------- tensor-core causal flash attention ------------------------
// QK^T in fp16 mma (m16n8k16), P@V in tf32 mma. BQ=128, BK=64, 8 warps.
__global__ void __launch_bounds__(256) flash_mma_kernel(const float* __restrict__ qkv,
                                                        __half* __restrict__ out)
{
    extern __shared__ float sm[];
    float* Qw = sm;                         // 128 rows x FQW(68) words (fp16 pairs)
    float* Kw = Qw + 128 * FQW;             // 64 x 68 words
    float* Vs = Kw + 64 * FQW;              // 64 x FVS floats (tf32)
    float* Ps = Vs + 64 * FVS;              // 128 x FPS floats (tf32)

    const int tid = threadIdx.x;
    const int wid = tid >> 5, lane = tid & 31;
    const int lq = lane >> 2, lr = lane & 3;
    const int b = blockIdx.z, h = blockIdx.y;
    const int q0 = ((int)gridDim.x - 1 - (int)blockIdx.x) * 128;   // heavy tiles first
    const float scale = 0.08838834764831845f;   // 1/sqrt(128)

    // load + scale + cvt Q tile (128 x 128 halves)
#pragma unroll
    for (int p = 0; p < 16; ++p) {
        const int f = tid + p * 256;
        const int r = f >> 5, c4 = (f & 31) << 2;   // 4 floats per thread
        float4 v = *(const float4*)(qkv + ((size_t)(b * SEQ + q0 + r)) * QKV_N + h * DHEAD + c4);
        uint2 o;
        o.x = pack2h(v.x * scale, v.y * scale);
        o.y = pack2h(v.z * scale, v.w * scale);
        *(uint2*)&Qw[r * FQW + (c4 >> 1)] = o;
    }

    float oacc[16][4];
#pragma unroll
    for (int nf = 0; nf < 16; ++nf)
#pragma unroll
        for (int q = 0; q < 4; ++q) oacc[nf][q] = 0.f;
    float m0v = -1e30f, m1v = -1e30f, l0v = 0.f, l1v = 0.f;

    const int ntiles = q0 / 64 + 2;
    for (int jt = 0; jt < ntiles; ++jt) {
        __syncthreads();   // previous tile's K/V reads done (also fences Qw on jt=0)
        // load K (fp16) + V (tf32) tiles, 64 x 128 each
#pragma unroll
        for (int p = 0; p < 8; ++p) {
            const int f = tid + p * 256;
            const int r = f >> 5, c4 = (f & 31) << 2;
            const float* base = qkv + ((size_t)(b * SEQ + jt * 64 + r)) * QKV_N;
            float4 kv = *(const float4*)(base + HDIM + c4);
            uint2 ok;
            ok.x = pack2h(kv.x, kv.y);
            ok.y = pack2h(kv.z, kv.w);
            *(uint2*)&Kw[r * FQW + (c4 >> 1)] = ok;
            float4 vv = *(const float4*)(base + HDIM + DHEAD + c4);
            float4 ov;
            ov.x = rndf(vv.x); ov.y = rndf(vv.y); ov.z = rndf(vv.z); ov.w = rndf(vv.w);
            *(float4*)&Vs[r * FVS + c4] = ov;
        }
        __syncthreads();

        // ---- S = Q @ K^T : fp16, 8 k16 steps over d=128 ----
        float sacc[8][4];
#pragma unroll
        for (int f = 0; f < 8; ++f)
#pragma unroll
            for (int q = 0; q < 4; ++q) sacc[f][q] = 0.f;

#pragma unroll
        for (int ks = 0; ks < 8; ++ks) {
            uint32_t af[4];
            const int abase = (wid * 16 + lq) * FQW + ks * 8 + lr;
            af[0] = __float_as_uint(Qw[abase]);
            af[1] = __float_as_uint(Qw[abase + 8 * FQW]);
            af[2] = __float_as_uint(Qw[abase + 4]);
            af[3] = __float_as_uint(Qw[abase + 8 * FQW + 4]);
#pragma unroll
            for (int f = 0; f < 8; ++f) {
                uint32_t bf[2];
                const int bbase = (f * 8 + lq) * FQW + ks * 8 + lr;
                bf[0] = __float_as_uint(Kw[bbase]);
                bf[1] = __float_as_uint(Kw[bbase + 4]);
                mma_f16(sacc[f], af, bf);
            }
        }

        // causal mask (only tiles intersecting the diagonal)
        if (jt * 64 + 63 > q0) {
            const int r0 = q0 + wid * 16 + lq;
#pragma unroll
            for (int f = 0; f < 8; ++f) {
                const int c0 = jt * 64 + f * 8 + 2 * lr;
                if (c0 > r0)     sacc[f][0] = -1e30f;
                if (c0 + 1 > r0) sacc[f][1] = -1e30f;
                if (c0 > r0 + 8)     sacc[f][2] = -1e30f;
                if (c0 + 1 > r0 + 8) sacc[f][3] = -1e30f;
            }
        }

        // ---- online softmax ----
        float mx0 = -1e30f, mx1 = -1e30f;
#pragma unroll
        for (int f = 0; f < 8; ++f) {
            mx0 = fmaxf(mx0, fmaxf(sacc[f][0], sacc[f][1]));
            mx1 = fmaxf(mx1, fmaxf(sacc[f][2], sacc[f][3]));
        }
        mx0 = fmaxf(mx0, __shfl_xor_sync(0xffffffffu, mx0, 1));
        mx0 = fmaxf(mx0, __shfl_xor_sync(0xffffffffu, mx0, 2));
        mx1 = fmaxf(mx1, __shfl_xor_sync(0xffffffffu, mx1, 1));
        mx1 = fmaxf(mx1, __shfl_xor_sync(0xffffffffu, mx1, 2));

        const float mn0 = fmaxf(m0v, mx0), mn1 = fmaxf(m1v, mx1);
        const float a0 = __expf(m0v - mn0), a1 = __expf(m1v - mn1);
        m0v = mn0; m1v = mn1;

        float s0 = 0.f, s1 = 0.f;
#pragma unroll
        for (int f = 0; f < 8; ++f) {
            sacc[f][0] = __expf(sacc[f][0] - mn0);
            sacc[f][1] = __expf(sacc[f][1] - mn0);
            sacc[f][2] = __expf(sacc[f][2] - mn1);
            sacc[f][3] = __expf(sacc[f][3] - mn1);
            s0 += sacc[f][0] + sacc[f][1];
            s1 += sacc[f][2] + sacc[f][3];
        }
        s0 += __shfl_xor_sync(0xffffffffu, s0, 1);
        s0 += __shfl_xor_sync(0xffffffffu, s0, 2);
        s1 += __shfl_xor_sync(0xffffffffu, s1, 1);
        s1 += __shfl_xor_sync(0xffffffffu, s1, 2);
        l0v = l0v * a0 + s0;
        l1v = l1v * a1 + s1;
#pragma unroll
        for (int nf = 0; nf < 16; ++nf) {
            oacc[nf][0] *= a0; oacc[nf][1] *= a0;
            oacc[nf][2] *= a1; oacc[nf][3] *= a1;
        }

        // store P fragments (tf32, warp-local region of Ps)
#pragma unroll
        for (int f = 0; f < 8; ++f) {
            float2 p0; p0.x = rndf(sacc[f][0]); p0.y = rndf(sacc[f][1]);
            *(float2*)&Ps[(wid * 16 + lq) * FPS + f * 8 + 2 * lr] = p0;
            float2 p1; p1.x = rndf(sacc[f][2]); p1.y = rndf(sacc[f][3]);
            *(float2*)&Ps[(wid * 16 + lq + 8) * FPS + f * 8 + 2 * lr] = p1;
        }
        __syncwarp();

        // ---- O += P @ V (tf32) ----
#pragma unroll
        for (int ks = 0; ks < 8; ++ks) {
            uint32_t pa[4];
            const int pbase = (wid * 16 + lq) * FPS + ks * 8 + lr;
            pa[0] = __float_as_uint(Ps[pbase]);
            pa[1] = __float_as_uint(Ps[pbase + 8 * FPS]);
            pa[2] = __float_as_uint(Ps[pbase + 4]);
            pa[3] = __float_as_uint(Ps[pbase + 8 * FPS + 4]);
#pragma unroll
            for (int nf = 0; nf < 16; ++nf) {
                uint32_t vb[2];
                const int vbase = (ks * 8 + lr) * FVS + nf * 8 + lq;
                vb[0] = __float_as_uint(Vs[vbase]);
                vb[1] = __float_as_uint(Vs[vbase + 4 * FVS]);
                mma_tf32(oacc[nf], pa, vb);
            }
        }
    }

    // epilogue: O /= l, cvt fp16 (pure O-proj GEMM A operand), packed layout
    const float inv0 = 1.f / l0v, inv1 = 1.f / l1v;
    const int r0 = q0 + wid * 16 + lq;
#pragma unroll
    for (int nf = 0; nf < 16; ++nf) {
        const int col = h * DHEAD + nf * 8 + 2 * lr;
        *(uint32_t*)(out + ((size_t)(b * SEQ + r0)) * HDIM + col)
            = pack2h(oacc[nf][0] * inv0, oacc[nf][1] * inv0);
        *(uint32_t*)(out + ((size_t)(b * SEQ + r0 + 8)) * HDIM + col)
            = pack2h(oacc[nf][2] * inv1, oacc[nf][3] * inv1);
    }
}

// ---------------- launcher ----------------
extern "C" void kernel_launch(void* const* d_in, const int* in_sizes, int n_in,
                              void* d_out, int out_size)
{
    int iwq, ibq, iwk, ibk, iwv, ibv, iwo, iwg, iwu, iwd, iln1, iln2, icos, isin;
    if (n_in >= 2 && in_sizes[1] == SEQ * SEQ) {
        icos = 2; isin = 3; iwq = 4; ibq = 5; iwk = 6; ibk = 7; iwv = 8; ibv = 9;
        iwo = 10; iwg = 11; iwu = 12; iwd = 13; iln1 = 14; iln2 = 15;
    } else {
        iwq = 1; ibq = 2; iwk = 3; ibk = 4; iwv = 5; ibv = 6; iwo = 7; iwg = 8;
        iwu = 9; iwd = 10; iln1 = 11; iln2 = 12; icos = 14; isin = 15;
    }

    const float* hs   = (const float*)d_in[0];
    const float* wq   = (const float*)d_in[iwq];
    const float* bq   = (const float*)d_in[ibq];
    const float* wk   = (const float*)d_in[iwk];
    const float* bk   = (const float*)d_in[ibk];
    const float* wv   = (const float*)d_in[iwv];
    const float* bv   = (const float*)d_in[ibv];
    const float* wo   = (const float*)d_in[iwo];
    const float* wg   = (const float*)d_in[iwg];
    const float* wu   = (const float*)d_in[iwu];
    const float* wd   = (const float*)d_in[iwd];
    const float* ln1  = (const float*)d_in[iln1];
    const float* ln2  = (const float*)d_in[iln2];
    const float* cosT = (const float*)d_in[icos];
    const float* sinT = (const float*)d_in[isin];

    float *p_qkv, *p_x2, *p_up, *p_bqkv;
    __half *p_h1h, *p_h2h, *p_attnh, *p_gah, *p_wqkvh, *p_wh;
    cudaGetSymbolAddress((void**)&p_qkv,   g_qkv);
    cudaGetSymbolAddress((void**)&p_x2,    g_x2);
    cudaGetSymbolAddress((void**)&p_up,    g_up);
    cudaGetSymbolAddress((void**)&p_bqkv,  g_bqkv);
    cudaGetSymbolAddress((void**)&p_h1h,   g_h1h);
    cudaGetSymbolAddress((void**)&p_h2h,   g_h2h);
    cudaGetSymbolAddress((void**)&p_attnh, g_attnh);
    cudaGetSymbolAddress((void**)&p_gah,   g_gah);
    cudaGetSymbolAddress((void**)&p_wqkvh, g_wqkvh);
    cudaGetSymbolAddress((void**)&p_wh,    g_wh);

    // bias concat (fp32)
    cudaMemcpyAsync(p_bqkv,                bq, HDIM  * 4, cudaMemcpyDeviceToDevice, 0);
    cudaMemcpyAsync(p_bqkv + HDIM,         bk, DHEAD * 4, cudaMemcpyDeviceToDevice, 0);
    cudaMemcpyAsync(p_bqkv + HDIM + DHEAD, bv, DHEAD * 4, cudaMemcpyDeviceToDevice, 0);

    // convert all weights to fp16 (concat wq|wk|wv into wqkvh)
    {
        int n4;
        n4 = HDIM * HDIM / 4;
        cvt_h_kernel<<<(n4 + 255) / 256, 256>>>(wq, p_wqkvh, n4);
        cvt_h_kernel<<<(n4 + 255) / 256, 256>>>(wo, p_wh + WO_OFF, n4);
        n4 = DHEAD * HDIM / 4;
        cvt_h_kernel<<<(n4 + 255) / 256, 256>>>(wk, p_wqkvh + HDIM * HDIM, n4);
        cvt_h_kernel<<<(n4 + 255) / 256, 256>>>(wv, p_wqkvh + (HDIM + DHEAD) * HDIM, n4);
        n4 = IDIM * HDIM / 4;
        cvt_h_kernel<<<(n4 + 255) / 256, 256>>>(wg, p_wh + WG_OFF, n4);
        cvt_h_kernel<<<(n4 + 255) / 256, 256>>>(wu, p_wh + WU_OFF, n4);
        cvt_h_kernel<<<(n4 + 255) / 256, 256>>>(wd, p_wh + WD_OFF, n4);
    }

    const int smem_gemm = 3 * 2 * 128 * GSTRIDE * 4;   // 110592 B
    cudaFuncSetAttribute(gemm_h<0>, cudaFuncAttributeMaxDynamicSharedMemorySize, smem_gemm);
    cudaFuncSetAttribute(gemm_h<1>, cudaFuncAttributeMaxDynamicSharedMemorySize, smem_gemm);
    cudaFuncSetAttribute(gemm_h<2>, cudaFuncAttributeMaxDynamicSharedMemorySize, smem_gemm);
    const int smem_flash = (128 * FQW + 64 * FQW + 64 * FVS + 128 * FPS) * 4;   // 121856 B
    cudaFuncSetAttribute(flash_mma_kernel, cudaFuncAttributeMaxDynamicSharedMemorySize, smem_flash);

    // 1) rmsnorm1 -> fp16
    rmsnorm_kernel<<<M_ROWS, 256>>>(hs, ln1, p_h1h);
    // 2) fused QKV projection (fp16 in, fp32 out + bias)
    gemm_h<0><<<dim3(QKV_N / 128, M_ROWS / 128), 256, smem_gemm>>>(
        p_h1h, p_wqkvh, p_bqkv, nullptr, p_qkv, M_ROWS, QKV_N, HDIM);
    // 3) RoPE (fp32)
    rope_kernel<<<dim3(M_ROWS, NHEADS + 1), 64>>>(p_qkv, cosT, sinT);
    // 4) flash attention (fp16 QK^T, tf32 PV) -> fp16 out
    flash_mma_kernel<<<dim3(SEQ / 128, NHEADS, 2), 256, smem_flash>>>(p_qkv, p_attnh);
    // 5) O projection + residual (fp32 out)
    gemm_h<1><<<dim3(HDIM / 128, M_ROWS / 128), 256, smem_gemm>>>(
        p_attnh, p_wh + WO_OFF, nullptr, hs, p_x2, M_ROWS, HDIM, HDIM);
    // 6) rmsnorm2 -> fp16
    rmsnorm_kernel<<<M_ROWS, 256>>>(p_x2, ln2, p_h2h);
    // 7) up projection (fp32 raw out; consumed as aux)
    gemm_h<0><<<dim3(IDIM / 128, M_ROWS / 128), 256, smem_gemm>>>(
        p_h2h, p_wh + WU_OFF, nullptr, nullptr, p_up, M_ROWS, IDIM, HDIM);
    // 8) gate projection + fused silu(gate)*up -> fp16
    gemm_h<2><<<dim3(IDIM / 128, M_ROWS / 128), 256, smem_gemm>>>(
        p_h2h, p_wh + WG_OFF, nullptr, p_up, (float*)p_gah, M_ROWS, IDIM, HDIM);
    // 9) down projection + residual -> output (fp32)
    gemm_h<1><<<dim3(HDIM / 128, M_ROWS / 128), 256, smem_gemm>>>(
        p_gah, p_wh + WD_OFF, nullptr, p_x2, (float*)d_out, M_ROWS, HDIM, IDIM);
    (void)out_size;
}

// round 15
// speedup vs baseline: 5.9672x; 1.3598x over previous
#include <cuda_runtime.h>
#include <cuda_fp16.h>
#include <math.h>
#include <stdint.h>

// ---------------- problem constants ----------------
#define M_ROWS 4096      // B*S
#define HDIM   896
#define DHEAD  128
#define NHEADS 7
#define SEQ    2048
#define QKV_N  1152      // 7*128 + 128 + 128
#define IDIM   4864

#define GSTRIDE 36       // gemm smem stride (32-bit words); 36 mod 32 == 4
#define FKS 68           // flash Q/K/V smem stride (words); 68 mod 32 == 4
#define FPW 36           // flash P smem stride (words)

// ---------------- scratch (device globals; no runtime alloc) ----------------
__device__ float  g_qkv [M_ROWS * QKV_N];
__device__ float  g_x2  [M_ROWS * HDIM];
__device__ __half g_h1h [M_ROWS * HDIM];
__device__ __half g_h2h [M_ROWS * HDIM];
__device__ __half g_attnh[M_ROWS * HDIM];
__device__ __half g_uph [(size_t)M_ROWS * IDIM];
__device__ __half g_gah [(size_t)M_ROWS * IDIM];
__device__ __half g_wqkvh[QKV_N * HDIM];
__device__ float  g_bqkv[QKV_N];
// half weight copies: wo | wg | wu | wd
#define WO_OFF 0
#define WG_OFF (HDIM * HDIM)
#define WU_OFF (WG_OFF + IDIM * HDIM)
#define WD_OFF (WU_OFF + IDIM * HDIM)
#define WRND_TOTAL (WD_OFF + IDIM * HDIM)
__device__ __half g_wh[WRND_TOTAL];

// ---------------- helpers ----------------
__device__ __forceinline__ uint32_t pack2h(float a, float b) {
    __half2 h = __floats2half2_rn(a, b);
    return *(uint32_t*)&h;
}
__device__ __forceinline__ void mma_f16(float* c, const uint32_t* a, const uint32_t* b) {
    asm volatile(
        "mma.sync.aligned.m16n8k16.row.col.f32.f16.f16.f32 "
        "{%0,%1,%2,%3}, {%4,%5,%6,%7}, {%8,%9}, {%0,%1,%2,%3};"
        : "+f"(c[0]), "+f"(c[1]), "+f"(c[2]), "+f"(c[3])
        : "r"(a[0]), "r"(a[1]), "r"(a[2]), "r"(a[3]), "r"(b[0]), "r"(b[1]));
}
__device__ __forceinline__ uint32_t smem_u32(const void* p) {
    uint32_t a;
    asm("{ .reg .u64 t; cvta.to.shared.u64 t, %1; cvt.u32.u64 %0, t; }" : "=r"(a) : "l"(p));
    return a;
}
__device__ __forceinline__ void cp16(uint32_t dst, const void* src) {
    asm volatile("cp.async.cg.shared.global [%0], [%1], 16;" :: "r"(dst), "l"(src));
}
#define LDM_X4(r0, r1, r2, r3, addr) \
    asm volatile("ldmatrix.sync.aligned.m8n8.x4.shared.b16 {%0,%1,%2,%3}, [%4];" \
        : "=r"(r0), "=r"(r1), "=r"(r2), "=r"(r3) : "r"(addr))
#define LDM_X4T(r0, r1, r2, r3, addr) \
    asm volatile("ldmatrix.sync.aligned.m8n8.x4.trans.shared.b16 {%0,%1,%2,%3}, [%4];" \
        : "=r"(r0), "=r"(r1), "=r"(r2), "=r"(r3) : "r"(addr))

// ---------------- fp32 -> fp16 weight conversion ----------------
__global__ void __launch_bounds__(256) cvt_h_kernel(const float* __restrict__ in,
                                                    __half* __restrict__ out, int n4)
{
    const int i = blockIdx.x * 256 + threadIdx.x;
    if (i < n4) {
        float4 v = ((const float4*)in)[i];
        uint2 o;
        o.x = pack2h(v.x, v.y);
        o.y = pack2h(v.z, v.w);
        ((uint2*)out)[i] = o;
    }
}

// ---------------- RMSNorm (fp16 output: pure GEMM A operand) ----------------
__global__ void __launch_bounds__(256) rmsnorm_kernel(const float* __restrict__ x,
                                                      const float* __restrict__ w,
                                                      __half* __restrict__ out)
{
    __shared__ float red[256];
    const int row = blockIdx.x;
    const float* xr = x + (size_t)row * HDIM;
    float ss = 0.f;
    for (int i = threadIdx.x; i < HDIM; i += 256) { float v = xr[i]; ss += v * v; }
    red[threadIdx.x] = ss;
    __syncthreads();
    for (int s = 128; s > 0; s >>= 1) {
        if (threadIdx.x < s) red[threadIdx.x] += red[threadIdx.x + s];
        __syncthreads();
    }
    const float inv = rsqrtf(red[0] / (float)HDIM + 1e-6f);
    __half* orow = out + (size_t)row * HDIM;
    for (int i = threadIdx.x; i < HDIM; i += 256)
        orow[i] = __float2half_rn(xr[i] * inv * w[i]);
}

// ---------------- fp16 mma GEMM, cp.async 3-stage + ldmatrix ----------------
// A,B half (K-major). 128x128 tile, 256 thr, k-chunk = 64 halves (32 words).
// MODE 0: +bias[n] -> fp32. MODE 1: +aux[m,n](fp32) -> fp32.
// MODE 2: silu(acc)*aux(HALF) -> half. MODE 3: plain -> half.
template<int MODE>
__global__ void __launch_bounds__(256) gemm_h(const __half* __restrict__ A,
                                              const __half* __restrict__ B,
                                              const float* __restrict__ bias,
                                              const void* __restrict__ aux,
                                              void* __restrict__ Cv,
                                              int M, int N, int K)
{
    extern __shared__ float sm[];
    const uint32_t sbase = smem_u32(sm);
    constexpr uint32_t STG = 2 * 128 * GSTRIDE;   // words per stage (A+B)

    const int tid = threadIdx.x;
    const int wid = tid >> 5, lane = tid & 31;
    const int lq = lane >> 2, lr = lane & 3;
    const int warp_m = wid >> 2, warp_n = wid & 3;
    const int rowbase = warp_m * 64, colbase = warp_n * 32;
    const int m0 = blockIdx.y * 128, n0 = blockIdx.x * 128;

    const int pr = tid >> 3;          // 0..31 (row step 32)
    const int pc = (tid & 7) << 2;    // word col 0..28 (16B per thread)

    // ldmatrix lane address components
    const int l7 = lane & 7;
    const int aRow = rowbase + l7 + ((lane & 8) ? 8 : 0);   // A: M0/M1 row split
    const int aKw  = (lane & 16) ? 4 : 0;                   // A: M2/M3 k split
    const int bRow = colbase + l7 + ((lane & 16) ? 8 : 0);  // B: n-pair split
    const int bKw  = (lane & 8) ? 4 : 0;                    // B: b0/b1 k split

    float acc[4][4][4];
#pragma unroll
    for (int i = 0; i < 4; i++)
#pragma unroll
        for (int j = 0; j < 4; j++)
#pragma unroll
            for (int q = 0; q < 4; q++) acc[i][j][q] = 0.f;

    const int nch = K >> 6;           // 64 halves per chunk
    const __half* Abase = A + (size_t)m0 * K;
    const __half* Bbase = B + (size_t)n0 * K;

#define ISSUE(CH, S) do { \
        const __half* Ap_ = Abase + (CH) * 64; \
        const __half* Bp_ = Bbase + (CH) * 64; \
        const uint32_t sA_ = sbase + (S) * STG * 4; \
        const uint32_t sB_ = sA_ + 128 * GSTRIDE * 4; \
        _Pragma("unroll") \
        for (int p_ = 0; p_ < 4; ++p_) { \
            const int r_ = pr + p_ * 32; \
            cp16(sA_ + (uint32_t)(r_ * GSTRIDE + pc) * 4, Ap_ + (size_t)r_ * K + pc * 2); \
            cp16(sB_ + (uint32_t)(r_ * GSTRIDE + pc) * 4, Bp_ + (size_t)r_ * K + pc * 2); \
        } \
    } while (0)

    ISSUE(0, 0);
    asm volatile("cp.async.commit_group;");
    if (nch > 1) ISSUE(1, 1);
    asm volatile("cp.async.commit_group;");

    for (int ch = 0; ch < nch; ++ch) {
        if (ch + 1 < nch) asm volatile("cp.async.wait_group 1;");
        else              asm volatile("cp.async.wait_group 0;");
        __syncthreads();
        if (ch + 2 < nch) {           // safe: overwritten stage's readers ran pre-barrier
            ISSUE(ch + 2, (ch + 2) % 3);
            asm volatile("cp.async.commit_group;");
        }

        const uint32_t sA = sbase + (uint32_t)(ch % 3) * STG * 4;
        const uint32_t sB = sA + 128 * GSTRIDE * 4;
#pragma unroll
        for (int ks = 0; ks < 4; ++ks) {    // 4 x k16
            uint32_t af[4][4], bf[4][2];
#pragma unroll
            for (int i = 0; i < 4; ++i)
                LDM_X4(af[i][0], af[i][1], af[i][2], af[i][3],
                       sA + (uint32_t)((aRow + i * 16) * GSTRIDE + ks * 8 + aKw) * 4);
#pragma unroll
            for (int jp = 0; jp < 2; ++jp)
                LDM_X4(bf[2 * jp][0], bf[2 * jp][1], bf[2 * jp + 1][0], bf[2 * jp + 1][1],
                       sB + (uint32_t)((bRow + jp * 16) * GSTRIDE + ks * 8 + bKw) * 4);
#pragma unroll
            for (int i = 0; i < 4; ++i)
#pragma unroll
                for (int j = 0; j < 4; ++j)
                    mma_f16(acc[i][j], af[i], bf[j]);
        }
    }
#undef ISSUE

    // epilogue
#pragma unroll
    for (int i = 0; i < 4; ++i) {
#pragma unroll
        for (int half_ = 0; half_ < 2; ++half_) {
            const int m = m0 + rowbase + i * 16 + lq + half_ * 8;
#pragma unroll
            for (int j = 0; j < 4; ++j) {
                const int n = n0 + colbase + j * 8 + 2 * lr;
                float v0 = acc[i][j][half_ * 2 + 0];
                float v1 = acc[i][j][half_ * 2 + 1];
                if (MODE == 0) {
                    if (bias) { v0 += bias[n]; v1 += bias[n + 1]; }
                    *(float2*)((float*)Cv + (size_t)m * N + n) = make_float2(v0, v1);
                } else if (MODE == 1) {
                    const float* arow = (const float*)aux + (size_t)m * N;
                    v0 += arow[n]; v1 += arow[n + 1];
                    *(float2*)((float*)Cv + (size_t)m * N + n) = make_float2(v0, v1);
                } else if (MODE == 2) {
                    const __half2 a2 = *(const __half2*)((const __half*)aux + (size_t)m * N + n);
                    const float2 af2 = __half22float2(a2);
                    v0 = v0 / (1.f + __expf(-v0)) * af2.x;
                    v1 = v1 / (1.f + __expf(-v1)) * af2.y;
                    *(uint32_t*)((__half*)Cv + (size_t)m * N + n) = pack2h(v0, v1);
                } else {
                    *(uint32_t*)((__half*)Cv + (size_t)m * N + n) = pack2h(v0, v1);
                }
            }
        }
    }
}

// ---------------- RoPE on q (7 heads) and k (1 head) ----------------
__global__ void rope_kernel(float* __restrict__ qkv,
                            const float* __restrict__ cosT,
                            const float* __restrict__ sinT)
{
    const int row  = blockIdx.x;
    const int unit = blockIdx.y;
    const int d    = threadIdx.x;
    const int s    = row & (SEQ - 1);
    const float c  = cosT[s * DHEAD + d];
    const float sn = sinT[s * DHEAD + d];
    float* p = qkv + (size_t)row * QKV_N + (unit < NHEADS ? unit * DHEAD : HDIM);
    const float x1 = p[d], x2 = p[d + 64];
    p[d]      = x1 * c  - x2 * sn;
    p[d + 64] = x1 * sn + x2 * c;
}

// ---------------- tensor-core causal flash attention (all-fp16 mma) ---------
// BQ=128, BK=64, 8 warps x 16 q-rows. QK^T and P@V both m16n8k16 f16.
__global__ void __launch_bounds__(256) flash_mma_kernel(const float* __restrict__ qkv,
                                                        __half* __restrict__ out)
{
    extern __shared__ float sm[];
    const uint32_t sbQ = smem_u32(sm);                       // 128 x FKS words
    const uint32_t sbK = sbQ + 128 * FKS * 4;                // 64 x FKS
    const uint32_t sbV = sbK + 64 * FKS * 4;                 // 64 x FKS (natural: key x d)
    const uint32_t sbP = sbV + 64 * FKS * 4;                 // 128 x FPW
    uint32_t* Qw = (uint32_t*)sm;
    uint32_t* Kw = Qw + 128 * FKS;
    uint32_t* Vw = Kw + 64 * FKS;
    uint32_t* Pw = Vw + 64 * FKS;

    const int tid = threadIdx.x;
    const int wid = tid >> 5, lane = tid & 31;
    const int lq = lane >> 2, lr = lane & 3;
    const int b = blockIdx.z, h = blockIdx.y;
    const int q0 = ((int)gridDim.x - 1 - (int)blockIdx.x) * 128;   // heavy tiles first
    const float scale = 0.08838834764831845f;   // 1/sqrt(128)

    // ldmatrix lane address components
    const int l7 = lane & 7;
    const int aRowOff = l7 + ((lane & 8) ? 8 : 0);     // A-pattern row split
    const int aKw     = (lane & 16) ? 4 : 0;           // A-pattern k split
    const int bRowOff = l7 + ((lane & 16) ? 8 : 0);    // B non-trans n-pair split
    const int bKw     = (lane & 8) ? 4 : 0;
    const int vK      = l7 + ((lane & 8) ? 8 : 0);     // V trans: k split
    const int vCol    = (lane & 16) ? 4 : 0;           // V trans: nf split

    // load + scale + cvt Q tile (128 x 128 halves)
#pragma unroll
    for (int p = 0; p < 16; ++p) {
        const int f = tid + p * 256;
        const int r = f >> 5, c4 = (f & 31) << 2;
        float4 v = *(const float4*)(qkv + ((size_t)(b * SEQ + q0 + r)) * QKV_N + h * DHEAD + c4);
        uint2 o;
        o.x = pack2h(v.x * scale, v.y * scale);
        o.y = pack2h(v.z * scale, v.w * scale);
        *(uint2*)&Qw[r * FKS + (c4 >> 1)] = o;
    }

    float oacc[16][4];
#pragma unroll
    for (int nf = 0; nf < 16; ++nf)
#pragma unroll
        for (int q = 0; q < 4; ++q) oacc[nf][q] = 0.f;
    float m0v = -1e30f, m1v = -1e30f, l0v = 0.f, l1v = 0.f;

    const int ntiles = q0 / 64 + 2;
    for (int jt = 0; jt < ntiles; ++jt) {
        __syncthreads();   // previous tile's K/V reads done (also fences Qw on jt=0)
#pragma unroll
        for (int p = 0; p < 8; ++p) {
            const int f = tid + p * 256;
            const int r = f >> 5, c4 = (f & 31) << 2;
            const float* base = qkv + ((size_t)(b * SEQ + jt * 64 + r)) * QKV_N;
            float4 kv = *(const float4*)(base + HDIM + c4);
            uint2 ok;
            ok.x = pack2h(kv.x, kv.y);
            ok.y = pack2h(kv.z, kv.w);
            *(uint2*)&Kw[r * FKS + (c4 >> 1)] = ok;
            float4 vv = *(const float4*)(base + HDIM + DHEAD + c4);
            uint2 ov;
            ov.x = pack2h(vv.x, vv.y);
            ov.y = pack2h(vv.z, vv.w);
            *(uint2*)&Vw[r * FKS + (c4 >> 1)] = ov;
        }
        __syncthreads();

        // ---- S = Q @ K^T : fp16, 8 k16 steps over d=128 ----
        float sacc[8][4];
#pragma unroll
        for (int f = 0; f < 8; ++f)
#pragma unroll
            for (int q = 0; q < 4; ++q) sacc[f][q] = 0.f;

#pragma unroll
        for (int ks = 0; ks < 8; ++ks) {
            uint32_t af[4];
            LDM_X4(af[0], af[1], af[2], af[3],
                   sbQ + (uint32_t)((wid * 16 + aRowOff) * FKS + ks * 8 + aKw) * 4);
#pragma unroll
            for (int fp = 0; fp < 4; ++fp) {
                uint32_t b0a, b1a, b0b, b1b;
                LDM_X4(b0a, b1a, b0b, b1b,
                       sbK + (uint32_t)((fp * 16 + bRowOff) * FKS + ks * 8 + bKw) * 4);
                uint32_t bfa[2] = { b0a, b1a }, bfb[2] = { b0b, b1b };
                mma_f16(sacc[2 * fp],     af, bfa);
                mma_f16(sacc[2 * fp + 1], af, bfb);
            }
        }

        // causal mask (only tiles intersecting the diagonal)
        if (jt * 64 + 63 > q0) {
            const int r0 = q0 + wid * 16 + lq;
#pragma unroll
            for (int f = 0; f < 8; ++f) {
                const int c0 = jt * 64 + f * 8 + 2 * lr;
                if (c0 > r0)     sacc[f][0] = -1e30f;
                if (c0 + 1 > r0) sacc[f][1] = -1e30f;
                if (c0 > r0 + 8)     sacc[f][2] = -1e30f;
                if (c0 + 1 > r0 + 8) sacc[f][3] = -1e30f;
            }
        }

        // ---- online softmax (rows lq / lq+8, reduce across lr quad) ----
        float mx0 = -1e30f, mx1 = -1e30f;
#pragma unroll
        for (int f = 0; f < 8; ++f) {
            mx0 = fmaxf(mx0, fmaxf(sacc[f][0], sacc[f][1]));
            mx1 = fmaxf(mx1, fmaxf(sacc[f][2], sacc[f][3]));
        }
        mx0 = fmaxf(mx0, __shfl_xor_sync(0xffffffffu, mx0, 1));
        mx0 = fmaxf(mx0, __shfl_xor_sync(0xffffffffu, mx0, 2));
        mx1 = fmaxf(mx1, __shfl_xor_sync(0xffffffffu, mx1, 1));
        mx1 = fmaxf(mx1, __shfl_xor_sync(0xffffffffu, mx1, 2));

        const float mn0 = fmaxf(m0v, mx0), mn1 = fmaxf(m1v, mx1);
        const float a0 = __expf(m0v - mn0), a1 = __expf(m1v - mn1);
        m0v = mn0; m1v = mn1;

        float s0 = 0.f, s1 = 0.f;
#pragma unroll
        for (int f = 0; f < 8; ++f) {
            sacc[f][0] = __expf(sacc[f][0] - mn0);
            sacc[f][1] = __expf(sacc[f][1] - mn0);
            sacc[f][2] = __expf(sacc[f][2] - mn1);
            sacc[f][3] = __expf(sacc[f][3] - mn1);
            s0 += sacc[f][0] + sacc[f][1];
            s1 += sacc[f][2] + sacc[f][3];
        }
        s0 += __shfl_xor_sync(0xffffffffu, s0, 1);
        s0 += __shfl_xor_sync(0xffffffffu, s0, 2);
        s1 += __shfl_xor_sync(0xffffffffu, s1, 1);
        s1 += __shfl_xor_sync(0xffffffffu, s1, 2);
        l0v = l0v * a0 + s0;
        l1v = l1v * a1 + s1;
#pragma unroll
        for (int nf = 0; nf < 16; ++nf) {
            oacc[nf][0] *= a0; oacc[nf][1] *= a0;
            oacc[nf][2] *= a1; oacc[nf][3] *= a1;
        }

        // store P as fp16 words (adjacent cols = adjacent k: direct pack2h)
#pragma unroll
        for (int f = 0; f < 8; ++f) {
            Pw[(wid * 16 + lq) * FPW + f * 4 + lr]     = pack2h(sacc[f][0], sacc[f][1]);
            Pw[(wid * 16 + lq + 8) * FPW + f * 4 + lr] = pack2h(sacc[f][2], sacc[f][3]);
        }
        __syncwarp();

        // ---- O += P @ V : fp16, 4 k16 steps over 64 keys ----
#pragma unroll
        for (int ks = 0; ks < 4; ++ks) {
            uint32_t pa[4];
            LDM_X4(pa[0], pa[1], pa[2], pa[3],
                   sbP + (uint32_t)((wid * 16 + aRowOff) * FPW + ks * 8 + aKw) * 4);
#pragma unroll
            for (int nfp = 0; nfp < 8; ++nfp) {
                uint32_t v0a, v1a, v0b, v1b;
                LDM_X4T(v0a, v1a, v0b, v1b,
                        sbV + (uint32_t)((ks * 16 + vK) * FKS + nfp * 8 + vCol) * 4);
                uint32_t vba[2] = { v0a, v1a }, vbb[2] = { v0b, v1b };
                mma_f16(oacc[2 * nfp],     pa, vba);
                mma_f16(oacc[2 * nfp + 1], pa, vbb);
            }
        }
    }

    // epilogue: O /= l, cvt fp16 (pure O-proj GEMM A operand), packed layout
    const float inv0 = 1.f / l0v, inv1 = 1.f / l1v;
    const int r0 = q0 + wid * 16 + lq;
#pragma unroll
    for (int nf = 0; nf < 16; ++nf) {
        const int col = h * DHEAD + nf * 8 + 2 * lr;
        *(uint32_t*)(out + ((size_t)(b * SEQ + r0)) * HDIM + col)
            = pack2h(oacc[nf][0] * inv0, oacc[nf][1] * inv0);
        *(uint32_t*)(out + ((size_t)(b * SEQ + r0 + 8)) * HDIM + col)
            = pack2h(oacc[nf][2] * inv1, oacc[nf][3] * inv1);
    }
}

// ---------------- launcher ----------------
extern "C" void kernel_launch(void* const* d_in, const int* in_sizes, int n_in,
                              void* d_out, int out_size)
{
    int iwq, ibq, iwk, ibk, iwv, ibv, iwo, iwg, iwu, iwd, iln1, iln2, icos, isin;
    if (n_in >= 2 && in_sizes[1] == SEQ * SEQ) {
        icos = 2; isin = 3; iwq = 4; ibq = 5; iwk = 6; ibk = 7; iwv = 8; ibv = 9;
        iwo = 10; iwg = 11; iwu = 12; iwd = 13; iln1 = 14; iln2 = 15;
    } else {
        iwq = 1; ibq = 2; iwk = 3; ibk = 4; iwv = 5; ibv = 6; iwo = 7; iwg = 8;
        iwu = 9; iwd = 10; iln1 = 11; iln2 = 12; icos = 14; isin = 15;
    }

    const float* hs   = (const float*)d_in[0];
    const float* wq   = (const float*)d_in[iwq];
    const float* bq   = (const float*)d_in[ibq];
    const float* wk   = (const float*)d_in[iwk];
    const float* bk   = (const float*)d_in[ibk];
    const float* wv   = (const float*)d_in[iwv];
    const float* bv   = (const float*)d_in[ibv];
    const float* wo   = (const float*)d_in[iwo];
    const float* wg   = (const float*)d_in[iwg];
    const float* wu   = (const float*)d_in[iwu];
    const float* wd   = (const float*)d_in[iwd];
    const float* ln1  = (const float*)d_in[iln1];
    const float* ln2  = (const float*)d_in[iln2];
    const float* cosT = (const float*)d_in[icos];
    const float* sinT = (const float*)d_in[isin];

    float *p_qkv, *p_x2, *p_bqkv;
    __half *p_h1h, *p_h2h, *p_attnh, *p_uph, *p_gah, *p_wqkvh, *p_wh;
    cudaGetSymbolAddress((void**)&p_qkv,   g_qkv);
    cudaGetSymbolAddress((void**)&p_x2,    g_x2);
    cudaGetSymbolAddress((void**)&p_bqkv,  g_bqkv);
    cudaGetSymbolAddress((void**)&p_h1h,   g_h1h);
    cudaGetSymbolAddress((void**)&p_h2h,   g_h2h);
    cudaGetSymbolAddress((void**)&p_attnh, g_attnh);
    cudaGetSymbolAddress((void**)&p_uph,   g_uph);
    cudaGetSymbolAddress((void**)&p_gah,   g_gah);
    cudaGetSymbolAddress((void**)&p_wqkvh, g_wqkvh);
    cudaGetSymbolAddress((void**)&p_wh,    g_wh);

    // bias concat (fp32)
    cudaMemcpyAsync(p_bqkv,                bq, HDIM  * 4, cudaMemcpyDeviceToDevice, 0);
    cudaMemcpyAsync(p_bqkv + HDIM,         bk, DHEAD * 4, cudaMemcpyDeviceToDevice, 0);
    cudaMemcpyAsync(p_bqkv + HDIM + DHEAD, bv, DHEAD * 4, cudaMemcpyDeviceToDevice, 0);

    // convert all weights to fp16 (concat wq|wk|wv into wqkvh)
    {
        int n4;
        n4 = HDIM * HDIM / 4;
        cvt_h_kernel<<<(n4 + 255) / 256, 256>>>(wq, p_wqkvh, n4);
        cvt_h_kernel<<<(n4 + 255) / 256, 256>>>(wo, p_wh + WO_OFF, n4);
        n4 = DHEAD * HDIM / 4;
        cvt_h_kernel<<<(n4 + 255) / 256, 256>>>(wk, p_wqkvh + HDIM * HDIM, n4);
        cvt_h_kernel<<<(n4 + 255) / 256, 256>>>(wv, p_wqkvh + (HDIM + DHEAD) * HDIM, n4);
        n4 = IDIM * HDIM / 4;
        cvt_h_kernel<<<(n4 + 255) / 256, 256>>>(wg, p_wh + WG_OFF, n4);
        cvt_h_kernel<<<(n4 + 255) / 256, 256>>>(wu, p_wh + WU_OFF, n4);
        cvt_h_kernel<<<(n4 + 255) / 256, 256>>>(wd, p_wh + WD_OFF, n4);
    }

    const int smem_gemm = 3 * 2 * 128 * GSTRIDE * 4;   // 110592 B
    cudaFuncSetAttribute(gemm_h<0>, cudaFuncAttributeMaxDynamicSharedMemorySize, smem_gemm);
    cudaFuncSetAttribute(gemm_h<1>, cudaFuncAttributeMaxDynamicSharedMemorySize, smem_gemm);
    cudaFuncSetAttribute(gemm_h<2>, cudaFuncAttributeMaxDynamicSharedMemorySize, smem_gemm);
    cudaFuncSetAttribute(gemm_h<3>, cudaFuncAttributeMaxDynamicSharedMemorySize, smem_gemm);
    const int smem_flash = (128 * FKS + 64 * FKS + 64 * FKS + 128 * FPW) * 4;   // 86528 B
    cudaFuncSetAttribute(flash_mma_kernel, cudaFuncAttributeMaxDynamicSharedMemorySize, smem_flash);

    // 1) rmsnorm1 -> fp16
    rmsnorm_kernel<<<M_ROWS, 256>>>(hs, ln1, p_h1h);
    // 2) fused QKV projection (fp16 in, fp32 out + bias)
    gemm_h<0><<<dim3(QKV_N / 128, M_ROWS / 128), 256, smem_gemm>>>(
        p_h1h, p_wqkvh, p_bqkv, nullptr, p_qkv, M_ROWS, QKV_N, HDIM);
    // 3) RoPE (fp32)
    rope_kernel<<<dim3(M_ROWS, NHEADS + 1), 64>>>(p_qkv, cosT, sinT);
    // 4) flash attention (all-fp16 mma) -> fp16 out
    flash_mma_kernel<<<dim3(SEQ / 128, NHEADS, 2), 256, smem_flash>>>(p_qkv, p_attnh);
    // 5) O projection + residual (fp32 out)
    gemm_h<1><<<dim3(HDIM / 128, M_ROWS / 128), 256, smem_gemm>>>(
        p_attnh, p_wh + WO_OFF, nullptr, hs, p_x2, M_ROWS, HDIM, HDIM);
    // 6) rmsnorm2 -> fp16
    rmsnorm_kernel<<<M_ROWS, 256>>>(p_x2, ln2, p_h2h);
    // 7) up projection -> fp16
    gemm_h<3><<<dim3(IDIM / 128, M_ROWS / 128), 256, smem_gemm>>>(
        p_h2h, p_wh + WU_OFF, nullptr, nullptr, p_uph, M_ROWS, IDIM, HDIM);
    // 8) gate projection + fused silu(gate)*up(fp16) -> fp16
    gemm_h<2><<<dim3(IDIM / 128, M_ROWS / 128), 256, smem_gemm>>>(
        p_h2h, p_wh + WG_OFF, nullptr, p_uph, p_gah, M_ROWS, IDIM, HDIM);
    // 9) down projection + residual -> output (fp32)
    gemm_h<1><<<dim3(HDIM / 128, M_ROWS / 128), 256, smem_gemm>>>(
        p_gah, p_wh + WD_OFF, nullptr, p_x2, (float*)d_out, M_ROWS, HDIM, IDIM);
    (void)out_size;
}

// round 16
// speedup vs baseline: 6.0930x; 1.0211x over previous
#include <cuda_runtime.h>
#include <cuda_fp16.h>
#include <math.h>
#include <stdint.h>

// ---------------- problem constants ----------------
#define M_ROWS 4096      // B*S
#define HDIM   896
#define DHEAD  128
#define NHEADS 7
#define SEQ    2048
#define QKV_N  1152      // 7*128 + 128 + 128
#define IDIM   4864

#define GSTRIDE 36       // gemm smem stride (32-bit words); 36 mod 32 == 4
#define FKS 68           // flash Q/K/V smem stride (words); 68 mod 32 == 4
#define FPW 36           // flash P smem stride (words)

// ---------------- scratch (device globals; no runtime alloc) ----------------
__device__ float  g_x2  [M_ROWS * HDIM];
__device__ __half g_h1h [M_ROWS * HDIM];
__device__ __half g_h2h [M_ROWS * HDIM];
__device__ __half g_attnh[M_ROWS * HDIM];
__device__ __half g_qkvh[M_ROWS * QKV_N];
__device__ __half g_gah [(size_t)M_ROWS * IDIM];
__device__ __half g_wqkvh[QKV_N * HDIM];
__device__ float  g_bqkv[QKV_N];
// half weight copies: wo | wgu (interleaved gate/up) | wd
#define WO_OFF 0
#define WGU_OFF (HDIM * HDIM)
#define WD_OFF (WGU_OFF + 2 * IDIM * HDIM)
#define WRND_TOTAL (WD_OFF + IDIM * HDIM)
__device__ __half g_wh[WRND_TOTAL];

// ---------------- helpers ----------------
__device__ __forceinline__ uint32_t pack2h(float a, float b) {
    __half2 h = __floats2half2_rn(a, b);
    return *(uint32_t*)&h;
}
__device__ __forceinline__ void mma_f16(float* c, const uint32_t* a, const uint32_t* b) {
    asm volatile(
        "mma.sync.aligned.m16n8k16.row.col.f32.f16.f16.f32 "
        "{%0,%1,%2,%3}, {%4,%5,%6,%7}, {%8,%9}, {%0,%1,%2,%3};"
        : "+f"(c[0]), "+f"(c[1]), "+f"(c[2]), "+f"(c[3])
        : "r"(a[0]), "r"(a[1]), "r"(a[2]), "r"(a[3]), "r"(b[0]), "r"(b[1]));
}
__device__ __forceinline__ uint32_t smem_u32(const void* p) {
    uint32_t a;
    asm("{ .reg .u64 t; cvta.to.shared.u64 t, %1; cvt.u32.u64 %0, t; }" : "=r"(a) : "l"(p));
    return a;
}
__device__ __forceinline__ void cp16(uint32_t dst, const void* src) {
    asm volatile("cp.async.cg.shared.global [%0], [%1], 16;" :: "r"(dst), "l"(src));
}
#define LDM_X4(r0, r1, r2, r3, addr) \
    asm volatile("ldmatrix.sync.aligned.m8n8.x4.shared.b16 {%0,%1,%2,%3}, [%4];" \
        : "=r"(r0), "=r"(r1), "=r"(r2), "=r"(r3) : "r"(addr))
#define LDM_X4T(r0, r1, r2, r3, addr) \
    asm volatile("ldmatrix.sync.aligned.m8n8.x4.trans.shared.b16 {%0,%1,%2,%3}, [%4];" \
        : "=r"(r0), "=r"(r1), "=r"(r2), "=r"(r3) : "r"(addr))

// ---------------- fp32 -> fp16 weight conversion ----------------
__global__ void __launch_bounds__(256) cvt_h_kernel(const float* __restrict__ in,
                                                    __half* __restrict__ out, int n4)
{
    const int i = blockIdx.x * 256 + threadIdx.x;
    if (i < n4) {
        float4 v = ((const float4*)in)[i];
        uint2 o;
        o.x = pack2h(v.x, v.y);
        o.y = pack2h(v.z, v.w);
        ((uint2*)out)[i] = o;
    }
}
// interleaved: in row r -> out row 2r+off (for merged gate/up weight)
__global__ void __launch_bounds__(256) cvt_h_int_kernel(const float* __restrict__ in,
                                                        __half* __restrict__ out, int off)
{
    const int i = blockIdx.x * 256 + threadIdx.x;   // 4-float chunk id
    const int n4 = IDIM * HDIM / 4;
    if (i < n4) {
        const int row = (i * 4) / HDIM;
        const int col = (i * 4) % HDIM;
        float4 v = ((const float4*)in)[i];
        uint2 o;
        o.x = pack2h(v.x, v.y);
        o.y = pack2h(v.z, v.w);
        *(uint2*)(out + (size_t)(2 * row + off) * HDIM + col) = o;
    }
}

// ---------------- RMSNorm (fp16 output: pure GEMM A operand) ----------------
__global__ void __launch_bounds__(256) rmsnorm_kernel(const float* __restrict__ x,
                                                      const float* __restrict__ w,
                                                      __half* __restrict__ out)
{
    __shared__ float red[256];
    const int row = blockIdx.x;
    const float* xr = x + (size_t)row * HDIM;
    float ss = 0.f;
    for (int i = threadIdx.x; i < HDIM; i += 256) { float v = xr[i]; ss += v * v; }
    red[threadIdx.x] = ss;
    __syncthreads();
    for (int s = 128; s > 0; s >>= 1) {
        if (threadIdx.x < s) red[threadIdx.x] += red[threadIdx.x + s];
        __syncthreads();
    }
    const float inv = rsqrtf(red[0] / (float)HDIM + 1e-6f);
    __half* orow = out + (size_t)row * HDIM;
    for (int i = threadIdx.x; i < HDIM; i += 256)
        orow[i] = __float2half_rn(xr[i] * inv * w[i]);
}

// ---------------- fp16 mma GEMM, cp.async 3-stage + ldmatrix ----------------
// A,B half (K-major). 128x128 tile, 256 thr, k-chunk = 64 halves (32 words).
// MODE 0: +bias[n] -> half. MODE 1: +aux[m,n](fp32) -> fp32.
// MODE 2: col pairs (gate,up): silu(v0)*v1 -> half at n/2 (out width N/2).
template<int MODE>
__global__ void __launch_bounds__(256) gemm_h(const __half* __restrict__ A,
                                              const __half* __restrict__ B,
                                              const float* __restrict__ bias,
                                              const void* __restrict__ aux,
                                              void* __restrict__ Cv,
                                              int M, int N, int K)
{
    extern __shared__ float sm[];
    const uint32_t sbase = smem_u32(sm);
    constexpr uint32_t STG = 2 * 128 * GSTRIDE;   // words per stage (A+B)

    const int tid = threadIdx.x;
    const int wid = tid >> 5, lane = tid & 31;
    const int lq = lane >> 2, lr = lane & 3;
    const int warp_m = wid >> 2, warp_n = wid & 3;
    const int rowbase = warp_m * 64, colbase = warp_n * 32;
    const int m0 = blockIdx.y * 128, n0 = blockIdx.x * 128;

    const int pr = tid >> 3;          // 0..31 (row step 32)
    const int pc = (tid & 7) << 2;    // word col 0..28 (16B per thread)

    const int l7 = lane & 7;
    const int aRow = rowbase + l7 + ((lane & 8) ? 8 : 0);
    const int aKw  = (lane & 16) ? 4 : 0;
    const int bRow = colbase + l7 + ((lane & 16) ? 8 : 0);
    const int bKw  = (lane & 8) ? 4 : 0;

    float acc[4][4][4];
#pragma unroll
    for (int i = 0; i < 4; i++)
#pragma unroll
        for (int j = 0; j < 4; j++)
#pragma unroll
            for (int q = 0; q < 4; q++) acc[i][j][q] = 0.f;

    const int nch = K >> 6;           // 64 halves per chunk
    const __half* Abase = A + (size_t)m0 * K;
    const __half* Bbase = B + (size_t)n0 * K;

#define ISSUE(CH, S) do { \
        const __half* Ap_ = Abase + (CH) * 64; \
        const __half* Bp_ = Bbase + (CH) * 64; \
        const uint32_t sA_ = sbase + (S) * STG * 4; \
        const uint32_t sB_ = sA_ + 128 * GSTRIDE * 4; \
        _Pragma("unroll") \
        for (int p_ = 0; p_ < 4; ++p_) { \
            const int r_ = pr + p_ * 32; \
            cp16(sA_ + (uint32_t)(r_ * GSTRIDE + pc) * 4, Ap_ + (size_t)r_ * K + pc * 2); \
            cp16(sB_ + (uint32_t)(r_ * GSTRIDE + pc) * 4, Bp_ + (size_t)r_ * K + pc * 2); \
        } \
    } while (0)

    ISSUE(0, 0);
    asm volatile("cp.async.commit_group;");
    if (nch > 1) ISSUE(1, 1);
    asm volatile("cp.async.commit_group;");

    for (int ch = 0; ch < nch; ++ch) {
        if (ch + 1 < nch) asm volatile("cp.async.wait_group 1;");
        else              asm volatile("cp.async.wait_group 0;");
        __syncthreads();
        if (ch + 2 < nch) {           // safe: overwritten stage's readers ran pre-barrier
            ISSUE(ch + 2, (ch + 2) % 3);
            asm volatile("cp.async.commit_group;");
        }

        const uint32_t sA = sbase + (uint32_t)(ch % 3) * STG * 4;
        const uint32_t sB = sA + 128 * GSTRIDE * 4;
#pragma unroll
        for (int ks = 0; ks < 4; ++ks) {    // 4 x k16
            uint32_t af[4][4], bf[4][2];
#pragma unroll
            for (int i = 0; i < 4; ++i)
                LDM_X4(af[i][0], af[i][1], af[i][2], af[i][3],
                       sA + (uint32_t)((aRow + i * 16) * GSTRIDE + ks * 8 + aKw) * 4);
#pragma unroll
            for (int jp = 0; jp < 2; ++jp)
                LDM_X4(bf[2 * jp][0], bf[2 * jp][1], bf[2 * jp + 1][0], bf[2 * jp + 1][1],
                       sB + (uint32_t)((bRow + jp * 16) * GSTRIDE + ks * 8 + bKw) * 4);
#pragma unroll
            for (int i = 0; i < 4; ++i)
#pragma unroll
                for (int j = 0; j < 4; ++j)
                    mma_f16(acc[i][j], af[i], bf[j]);
        }
    }
#undef ISSUE

    // epilogue
#pragma unroll
    for (int i = 0; i < 4; ++i) {
#pragma unroll
        for (int half_ = 0; half_ < 2; ++half_) {
            const int m = m0 + rowbase + i * 16 + lq + half_ * 8;
#pragma unroll
            for (int j = 0; j < 4; ++j) {
                const int n = n0 + colbase + j * 8 + 2 * lr;
                float v0 = acc[i][j][half_ * 2 + 0];
                float v1 = acc[i][j][half_ * 2 + 1];
                if (MODE == 0) {
                    v0 += bias[n]; v1 += bias[n + 1];
                    *(uint32_t*)((__half*)Cv + (size_t)m * N + n) = pack2h(v0, v1);
                } else if (MODE == 1) {
                    const float* arow = (const float*)aux + (size_t)m * N;
                    v0 += arow[n]; v1 += arow[n + 1];
                    *(float2*)((float*)Cv + (size_t)m * N + n) = make_float2(v0, v1);
                } else {
                    // (gate, up) pair -> silu(gate)*up at col n/2
                    const float r = v0 / (1.f + __expf(-v0)) * v1;
                    ((__half*)Cv)[(size_t)m * (N >> 1) + (n >> 1)] = __float2half_rn(r);
                }
            }
        }
    }
}

// ---------------- RoPE (fp16 in-place; q heads pre-scaled by 1/sqrt(d)) -----
__global__ void rope_h_kernel(__half* __restrict__ qkv,
                              const float* __restrict__ cosT,
                              const float* __restrict__ sinT)
{
    const int row  = blockIdx.x;
    const int unit = blockIdx.y;     // 0..6 q heads, 7 = k
    const int d    = threadIdx.x;    // 0..63
    const int s    = row & (SEQ - 1);
    const float c  = cosT[s * DHEAD + d];
    const float sn = sinT[s * DHEAD + d];
    __half* p = qkv + (size_t)row * QKV_N + (unit < NHEADS ? unit * DHEAD : HDIM);
    const float x1 = __half2float(p[d]), x2 = __half2float(p[d + 64]);
    float r1 = x1 * c - x2 * sn;
    float r2 = x1 * sn + x2 * c;
    if (unit < NHEADS) {
        r1 *= 0.08838834764831845f;
        r2 *= 0.08838834764831845f;
    }
    p[d]      = __float2half_rn(r1);
    p[d + 64] = __float2half_rn(r2);
}

// ---------------- tensor-core causal flash attention (all-fp16 mma) ---------
// fp16 qkv input (Q pre-scaled). BQ=128, BK=64, 8 warps x 16 q-rows.
// K/V tiles double-buffered via cp.async.
__global__ void __launch_bounds__(256) flash_mma_kernel(const __half* __restrict__ qkv,
                                                        __half* __restrict__ out)
{
    extern __shared__ float sm[];
    const uint32_t sbQ = smem_u32(sm);                        // 128 x FKS words
    const uint32_t sbK0 = sbQ + 128 * FKS * 4;                // 64 x FKS per buf
    const uint32_t sbV0 = sbK0 + 2 * 64 * FKS * 4;
    const uint32_t sbP = sbV0 + 2 * 64 * FKS * 4;             // 128 x FPW
    uint32_t* Pw = (uint32_t*)sm + (sbP - sbQ) / 4;

    const int tid = threadIdx.x;
    const int wid = tid >> 5, lane = tid & 31;
    const int lq = lane >> 2, lr = lane & 3;
    const int b = blockIdx.z, h = blockIdx.y;
    const int q0 = ((int)gridDim.x - 1 - (int)blockIdx.x) * 128;   // heavy tiles first

    const int l7 = lane & 7;
    const int aRowOff = l7 + ((lane & 8) ? 8 : 0);
    const int aKw     = (lane & 16) ? 4 : 0;
    const int bRowOff = l7 + ((lane & 16) ? 8 : 0);
    const int bKw     = (lane & 8) ? 4 : 0;
    const int vK      = l7 + ((lane & 8) ? 8 : 0);
    const int vCol    = (lane & 16) ? 4 : 0;

    // producer indexing: 16B chunks; 16 chunks per 128-half row
    const int crow = tid >> 4;           // 0..15
    const int cw   = (tid & 15) << 2;    // word offset 0..60

    // Q tile: 128 rows x 256B = 2048 chunks, 8 per thread
#define ISSUE_Q() do { \
        _Pragma("unroll") \
        for (int p_ = 0; p_ < 8; ++p_) { \
            const int r_ = crow + p_ * 16; \
            cp16(sbQ + (uint32_t)(r_ * FKS + cw) * 4, \
                 qkv + ((size_t)(b * SEQ + q0 + r_)) * QKV_N + h * DHEAD + cw * 2); \
        } \
    } while (0)
    // K/V tile jt: 64 rows each, 4 chunks/thread each
#define ISSUE_KV(JT, S) do { \
        const uint32_t sK_ = sbK0 + (S) * 64 * FKS * 4; \
        const uint32_t sV_ = sbV0 + (S) * 64 * FKS * 4; \
        _Pragma("unroll") \
        for (int p_ = 0; p_ < 4; ++p_) { \
            const int r_ = crow + p_ * 16; \
            const __half* base_ = qkv + ((size_t)(b * SEQ + (JT) * 64 + r_)) * QKV_N; \
            cp16(sK_ + (uint32_t)(r_ * FKS + cw) * 4, base_ + HDIM + cw * 2); \
            cp16(sV_ + (uint32_t)(r_ * FKS + cw) * 4, base_ + HDIM + DHEAD + cw * 2); \
        } \
    } while (0)

    float oacc[16][4];
#pragma unroll
    for (int nf = 0; nf < 16; ++nf)
#pragma unroll
        for (int q = 0; q < 4; ++q) oacc[nf][q] = 0.f;
    float m0v = -1e30f, m1v = -1e30f, l0v = 0.f, l1v = 0.f;

    ISSUE_Q();
    ISSUE_KV(0, 0);
    asm volatile("cp.async.commit_group;");

    const int ntiles = q0 / 64 + 2;
    for (int jt = 0; jt < ntiles; ++jt) {
        const int buf = jt & 1;
        asm volatile("cp.async.wait_group 0;");
        __syncthreads();
        if (jt + 1 < ntiles) {        // safe post-barrier: buf^1 readers finished
            ISSUE_KV(jt + 1, buf ^ 1);
            asm volatile("cp.async.commit_group;");
        }
        const uint32_t sbK = sbK0 + (uint32_t)buf * 64 * FKS * 4;
        const uint32_t sbV = sbV0 + (uint32_t)buf * 64 * FKS * 4;

        // ---- S = Q @ K^T : fp16, 8 k16 steps over d=128 ----
        float sacc[8][4];
#pragma unroll
        for (int f = 0; f < 8; ++f)
#pragma unroll
            for (int q = 0; q < 4; ++q) sacc[f][q] = 0.f;

#pragma unroll
        for (int ks = 0; ks < 8; ++ks) {
            uint32_t af[4];
            LDM_X4(af[0], af[1], af[2], af[3],
                   sbQ + (uint32_t)((wid * 16 + aRowOff) * FKS + ks * 8 + aKw) * 4);
#pragma unroll
            for (int fp = 0; fp < 4; ++fp) {
                uint32_t b0a, b1a, b0b, b1b;
                LDM_X4(b0a, b1a, b0b, b1b,
                       sbK + (uint32_t)((fp * 16 + bRowOff) * FKS + ks * 8 + bKw) * 4);
                uint32_t bfa[2] = { b0a, b1a }, bfb[2] = { b0b, b1b };
                mma_f16(sacc[2 * fp],     af, bfa);
                mma_f16(sacc[2 * fp + 1], af, bfb);
            }
        }

        // causal mask
        if (jt * 64 + 63 > q0) {
            const int r0 = q0 + wid * 16 + lq;
#pragma unroll
            for (int f = 0; f < 8; ++f) {
                const int c0 = jt * 64 + f * 8 + 2 * lr;
                if (c0 > r0)     sacc[f][0] = -1e30f;
                if (c0 + 1 > r0) sacc[f][1] = -1e30f;
                if (c0 > r0 + 8)     sacc[f][2] = -1e30f;
                if (c0 + 1 > r0 + 8) sacc[f][3] = -1e30f;
            }
        }

        // ---- online softmax ----
        float mx0 = -1e30f, mx1 = -1e30f;
#pragma unroll
        for (int f = 0; f < 8; ++f) {
            mx0 = fmaxf(mx0, fmaxf(sacc[f][0], sacc[f][1]));
            mx1 = fmaxf(mx1, fmaxf(sacc[f][2], sacc[f][3]));
        }
        mx0 = fmaxf(mx0, __shfl_xor_sync(0xffffffffu, mx0, 1));
        mx0 = fmaxf(mx0, __shfl_xor_sync(0xffffffffu, mx0, 2));
        mx1 = fmaxf(mx1, __shfl_xor_sync(0xffffffffu, mx1, 1));
        mx1 = fmaxf(mx1, __shfl_xor_sync(0xffffffffu, mx1, 2));

        const float mn0 = fmaxf(m0v, mx0), mn1 = fmaxf(m1v, mx1);
        const float a0 = __expf(m0v - mn0), a1 = __expf(m1v - mn1);
        m0v = mn0; m1v = mn1;

        float s0 = 0.f, s1 = 0.f;
#pragma unroll
        for (int f = 0; f < 8; ++f) {
            sacc[f][0] = __expf(sacc[f][0] - mn0);
            sacc[f][1] = __expf(sacc[f][1] - mn0);
            sacc[f][2] = __expf(sacc[f][2] - mn1);
            sacc[f][3] = __expf(sacc[f][3] - mn1);
            s0 += sacc[f][0] + sacc[f][1];
            s1 += sacc[f][2] + sacc[f][3];
        }
        s0 += __shfl_xor_sync(0xffffffffu, s0, 1);
        s0 += __shfl_xor_sync(0xffffffffu, s0, 2);
        s1 += __shfl_xor_sync(0xffffffffu, s1, 1);
        s1 += __shfl_xor_sync(0xffffffffu, s1, 2);
        l0v = l0v * a0 + s0;
        l1v = l1v * a1 + s1;
#pragma unroll
        for (int nf = 0; nf < 16; ++nf) {
            oacc[nf][0] *= a0; oacc[nf][1] *= a0;
            oacc[nf][2] *= a1; oacc[nf][3] *= a1;
        }

        // store P as fp16 words
#pragma unroll
        for (int f = 0; f < 8; ++f) {
            Pw[(wid * 16 + lq) * FPW + f * 4 + lr]     = pack2h(sacc[f][0], sacc[f][1]);
            Pw[(wid * 16 + lq + 8) * FPW + f * 4 + lr] = pack2h(sacc[f][2], sacc[f][3]);
        }
        __syncwarp();

        // ---- O += P @ V : fp16 ----
#pragma unroll
        for (int ks = 0; ks < 4; ++ks) {
            uint32_t pa[4];
            LDM_X4(pa[0], pa[1], pa[2], pa[3],
                   sbP + (uint32_t)((wid * 16 + aRowOff) * FPW + ks * 8 + aKw) * 4);
#pragma unroll
            for (int nfp = 0; nfp < 8; ++nfp) {
                uint32_t v0a, v1a, v0b, v1b;
                LDM_X4T(v0a, v1a, v0b, v1b,
                        sbV + (uint32_t)((ks * 16 + vK) * FKS + nfp * 8 + vCol) * 4);
                uint32_t vba[2] = { v0a, v1a }, vbb[2] = { v0b, v1b };
                mma_f16(oacc[2 * nfp],     pa, vba);
                mma_f16(oacc[2 * nfp + 1], pa, vbb);
            }
        }
    }
#undef ISSUE_Q
#undef ISSUE_KV

    // epilogue: O /= l, cvt fp16, packed layout
    const float inv0 = 1.f / l0v, inv1 = 1.f / l1v;
    const int r0 = q0 + wid * 16 + lq;
#pragma unroll
    for (int nf = 0; nf < 16; ++nf) {
        const int col = h * DHEAD + nf * 8 + 2 * lr;
        *(uint32_t*)(out + ((size_t)(b * SEQ + r0)) * HDIM + col)
            = pack2h(oacc[nf][0] * inv0, oacc[nf][1] * inv0);
        *(uint32_t*)(out + ((size_t)(b * SEQ + r0 + 8)) * HDIM + col)
            = pack2h(oacc[nf][2] * inv1, oacc[nf][3] * inv1);
    }
}

// ---------------- launcher ----------------
extern "C" void kernel_launch(void* const* d_in, const int* in_sizes, int n_in,
                              void* d_out, int out_size)
{
    int iwq, ibq, iwk, ibk, iwv, ibv, iwo, iwg, iwu, iwd, iln1, iln2, icos, isin;
    if (n_in >= 2 && in_sizes[1] == SEQ * SEQ) {
        icos = 2; isin = 3; iwq = 4; ibq = 5; iwk = 6; ibk = 7; iwv = 8; ibv = 9;
        iwo = 10; iwg = 11; iwu = 12; iwd = 13; iln1 = 14; iln2 = 15;
    } else {
        iwq = 1; ibq = 2; iwk = 3; ibk = 4; iwv = 5; ibv = 6; iwo = 7; iwg = 8;
        iwu = 9; iwd = 10; iln1 = 11; iln2 = 12; icos = 14; isin = 15;
    }

    const float* hs   = (const float*)d_in[0];
    const float* wq   = (const float*)d_in[iwq];
    const float* bq   = (const float*)d_in[ibq];
    const float* wk   = (const float*)d_in[iwk];
    const float* bk   = (const float*)d_in[ibk];
    const float* wv   = (const float*)d_in[iwv];
    const float* bv   = (const float*)d_in[ibv];
    const float* wo   = (const float*)d_in[iwo];
    const float* wg   = (const float*)d_in[iwg];
    const float* wu   = (const float*)d_in[iwu];
    const float* wd   = (const float*)d_in[iwd];
    const float* ln1  = (const float*)d_in[iln1];
    const float* ln2  = (const float*)d_in[iln2];
    const float* cosT = (const float*)d_in[icos];
    const float* sinT = (const float*)d_in[isin];

    float *p_x2, *p_bqkv;
    __half *p_h1h, *p_h2h, *p_attnh, *p_qkvh, *p_gah, *p_wqkvh, *p_wh;
    cudaGetSymbolAddress((void**)&p_x2,    g_x2);
    cudaGetSymbolAddress((void**)&p_bqkv,  g_bqkv);
    cudaGetSymbolAddress((void**)&p_h1h,   g_h1h);
    cudaGetSymbolAddress((void**)&p_h2h,   g_h2h);
    cudaGetSymbolAddress((void**)&p_attnh, g_attnh);
    cudaGetSymbolAddress((void**)&p_qkvh,  g_qkvh);
    cudaGetSymbolAddress((void**)&p_gah,   g_gah);
    cudaGetSymbolAddress((void**)&p_wqkvh, g_wqkvh);
    cudaGetSymbolAddress((void**)&p_wh,    g_wh);

    // bias concat (fp32)
    cudaMemcpyAsync(p_bqkv,                bq, HDIM  * 4, cudaMemcpyDeviceToDevice, 0);
    cudaMemcpyAsync(p_bqkv + HDIM,         bk, DHEAD * 4, cudaMemcpyDeviceToDevice, 0);
    cudaMemcpyAsync(p_bqkv + HDIM + DHEAD, bv, DHEAD * 4, cudaMemcpyDeviceToDevice, 0);

    // convert weights to fp16: wq|wk|wv concat; wo; wd; wg/wu row-interleaved
    {
        int n4;
        n4 = HDIM * HDIM / 4;
        cvt_h_kernel<<<(n4 + 255) / 256, 256>>>(wq, p_wqkvh, n4);
        cvt_h_kernel<<<(n4 + 255) / 256, 256>>>(wo, p_wh + WO_OFF, n4);
        n4 = DHEAD * HDIM / 4;
        cvt_h_kernel<<<(n4 + 255) / 256, 256>>>(wk, p_wqkvh + HDIM * HDIM, n4);
        cvt_h_kernel<<<(n4 + 255) / 256, 256>>>(wv, p_wqkvh + (HDIM + DHEAD) * HDIM, n4);
        n4 = IDIM * HDIM / 4;
        cvt_h_int_kernel<<<(n4 + 255) / 256, 256>>>(wg, p_wh + WGU_OFF, 0);
        cvt_h_int_kernel<<<(n4 + 255) / 256, 256>>>(wu, p_wh + WGU_OFF, 1);
        cvt_h_kernel<<<(n4 + 255) / 256, 256>>>(wd, p_wh + WD_OFF, n4);
    }

    const int smem_gemm = 3 * 2 * 128 * GSTRIDE * 4;   // 110592 B
    cudaFuncSetAttribute(gemm_h<0>, cudaFuncAttributeMaxDynamicSharedMemorySize, smem_gemm);
    cudaFuncSetAttribute(gemm_h<1>, cudaFuncAttributeMaxDynamicSharedMemorySize, smem_gemm);
    cudaFuncSetAttribute(gemm_h<2>, cudaFuncAttributeMaxDynamicSharedMemorySize, smem_gemm);
    const int smem_flash = (128 * FKS + 4 * 64 * FKS + 128 * FPW) * 4;   // 122880 B
    cudaFuncSetAttribute(flash_mma_kernel, cudaFuncAttributeMaxDynamicSharedMemorySize, smem_flash);

    // 1) rmsnorm1 -> fp16
    rmsnorm_kernel<<<M_ROWS, 256>>>(hs, ln1, p_h1h);
    // 2) fused QKV projection -> fp16 (+bias)
    gemm_h<0><<<dim3(QKV_N / 128, M_ROWS / 128), 256, smem_gemm>>>(
        p_h1h, p_wqkvh, p_bqkv, nullptr, p_qkvh, M_ROWS, QKV_N, HDIM);
    // 3) RoPE fp16 in-place (q pre-scaled by 1/sqrt(d))
    rope_h_kernel<<<dim3(M_ROWS, NHEADS + 1), 64>>>(p_qkvh, cosT, sinT);
    // 4) flash attention (all-fp16, cp.async K/V pipeline) -> fp16
    flash_mma_kernel<<<dim3(SEQ / 128, NHEADS, 2), 256, smem_flash>>>(p_qkvh, p_attnh);
    // 5) O projection + residual -> fp32
    gemm_h<1><<<dim3(HDIM / 128, M_ROWS / 128), 256, smem_gemm>>>(
        p_attnh, p_wh + WO_OFF, nullptr, hs, p_x2, M_ROWS, HDIM, HDIM);
    // 6) rmsnorm2 -> fp16
    rmsnorm_kernel<<<M_ROWS, 256>>>(p_x2, ln2, p_h2h);
    // 7) merged gate+up projection (interleaved weights), fused silu*up -> fp16
    gemm_h<2><<<dim3(2 * IDIM / 128, M_ROWS / 128), 256, smem_gemm>>>(
        p_h2h, p_wh + WGU_OFF, nullptr, nullptr, p_gah, M_ROWS, 2 * IDIM, HDIM);
    // 8) down projection + residual -> output (fp32)
    gemm_h<1><<<dim3(HDIM / 128, M_ROWS / 128), 256, smem_gemm>>>(
        p_gah, p_wh + WD_OFF, nullptr, p_x2, (float*)d_out, M_ROWS, HDIM, IDIM);
    (void)out_size;
}